// round 14
// baseline (speedup 1.0000x reference)
#include <cuda_runtime.h>
#include <cstdint>

// ---------------- problem constants ----------------
#define NZ 9
#define ND 108          // depth cells (conv W dim)
#define NWC 124         // width cells (conv H dim)
#define NCELL 13392     // ND*NWC
#define IMC_ 256
#define HC_ 2304        // 9*256
#define CATC 1280
#define OH1 62
#define OW1 54
#define OSP 3348        // 62*54

// level geometry
__device__ __constant__ int c_HH[5] = { 96, 48, 24, 12, 6 };
__device__ __constant__ int c_WW[5] = { 320, 160, 80, 40, 20 };
// float-offsets of per-level P buffers (HW*2304)
__device__ __constant__ int c_POFF[5]  = { 0, 70778880, 88473600, 92897280, 94003200 };
// float-offsets of per-level rounded-feat buffers (HW*256)
__device__ __constant__ int c_FOFF[5]  = { 0, 7864320, 9830400, 10321920, 10444800 };
// cumulative float4 counts for merged k_round
__device__ __constant__ int c_FR4[6] = { 0, 1966080, 2457600, 2580480, 2611200, 2618880 };
// cumulative M-tile (128) counts per level for the fused GEMM
__device__ __constant__ int c_MTCUM[6] = { 0, 240, 300, 315, 319, 320 };
// cumulative thread counts for merged float4 cumsum kernels
__device__ __constant__ int c_RCUM4[6] = { 0, 55296, 82944, 96768, 103680, 107136 };
__device__ __constant__ int c_CCUM4[6] = { 0, 184320, 276480, 322560, 345600, 357120 };

// ---------------- scratch (device globals; no allocs allowed) ----------------
__device__ __align__(16) float g_P[94279680];       // all 5 levels, [z][hw][256] projected maps -> integral
__device__ __align__(16) float g_fr[10475520];      // tf32-rounded feats, all levels [c][hw]
__device__ __align__(16) float g_ctab[5 * NCELL * 12];    // col-tap table per (l,n)
__device__ __align__(16) float g_rtab[5 * NZ * ND * 12];  // row-tap table per (l,z,d)
__device__ __align__(16) float g_wb[5 * 256 * HC_];   // [l][c][z*256+o] tf32-rounded weights
__device__ __align__(16) float g_xcat[CATC * NCELL];  // concat ortho [1280][124][108]
__device__ __align__(16) float g_w1s[CATC * 9 * IMC_];
__device__ __align__(16) float g_w2p[IMC_ * 9 * IMC_];
__device__ float g_colmean[CATC];
__device__ float g_sig[CATC];
__device__ __align__(16) float g_y1[IMC_ * OSP];
__device__ __align__(16) float g_c1part[8 * IMC_ * OSP];
__device__ __align__(16) float g_c2part[4 * IMC_ * OSP];

__device__ __forceinline__ float to_tf32(float x) {
    float r;
    asm("cvt.rna.tf32.f32 %0, %1;" : "=f"(r) : "f"(x));
    return r;
}

__device__ __forceinline__ void cpa16(uint32_t dst, const float* src, bool pred) {
    asm volatile("cp.async.cg.shared.global [%0], [%1], 16, %2;"
                 :: "r"(dst), "l"(src), "r"(pred ? 16 : 0));
}
#define CP_COMMIT() asm volatile("cp.async.commit_group;" ::: "memory")
#define CP_WAIT1()  asm volatile("cp.async.wait_group 1;" ::: "memory")

// ---------------- corner projection (normalized, clamped) ----------------
__device__ __forceinline__ float2 projnc(const float* __restrict__ P, int zi, int di, int wi) {
    float X = 0.64f * (float)di;
    float Y = 39.68f - 0.64f * (float)wi;
    float Z = 2.76f - 0.64f * (float)zi;
    float hx = P[0] * X + P[1] * Y + P[2]  * Z + P[3];
    float hy = P[4] * X + P[5] * Y + P[6]  * Z + P[7];
    float hz = P[8] * X + P[9] * Y + P[10] * Z + P[11];
    float ix = hx / hz, iy = hy / hz;
    float nx = fminf(fmaxf(2.0f * ix / 1280.0f - 1.0f, -1.0f), 1.0f);
    float ny = fminf(fmaxf(2.0f * iy / 384.0f  - 1.0f, -1.0f), 1.0f);
    return make_float2(nx, ny);
}

// ---------------- merged: pre-round all feats to tf32 ----------------
__global__ void k_round(const float* __restrict__ f0, const float* __restrict__ f1,
                        const float* __restrict__ f2, const float* __restrict__ f3,
                        const float* __restrict__ f4) {
    int i = blockIdx.x * 256 + threadIdx.x;
    if (i >= 2618880) return;
    int l = 0;
    while (i >= c_FR4[l + 1]) l++;
    int ii = i - c_FR4[l];
    const float* f = (l == 0) ? f0 : (l == 1) ? f1 : (l == 2) ? f2 : (l == 3) ? f3 : f4;
    float4 v = ((const float4*)f)[ii];
    v.x = to_tf32(v.x); v.y = to_tf32(v.y); v.z = to_tf32(v.z); v.w = to_tf32(v.w);
    ((float4*)(g_fr + c_FOFF[l]))[ii] = v;
}

// ---------------- merged tap tables: ctab (5*NCELL) then rtab (5*NZ*ND) ----------------
__global__ void k_tab(const float* __restrict__ P) {
    int gidx = blockIdx.x * 256 + threadIdx.x;
    if (gidx < 5 * NCELL) {
        int idx = gidx;
        int n = idx % NCELL;
        int l = idx / NCELL;
        int d = n / NWC, w = n - d * NWC;
        int Wf = c_WW[l];

        float xa = projnc(P, 0, d,     w).x;
        float xb = projnc(P, 0, d + 1, w).x;
        float xc = projnc(P, 0, d + 1, w + 1).x;
        float xd = projnc(P, 0, d,     w + 1).x;
        float x1 = fminf(xa, xb);
        float x2 = fmaxf(xc, xd);

        float xp1 = (x1 + 1.f) * (Wf * 0.5f) - 0.5f;
        float xf1 = floorf(xp1); float wx1 = xp1 - xf1; int xi1 = (int)xf1;
        float xp2 = (x2 + 1.f) * (Wf * 0.5f) - 0.5f;
        float xf2 = floorf(xp2); float wx2 = xp2 - xf2; int xi2 = (int)xf2;

        float cw[4]; int co[4]; int ncol;
        if (xi2 == xi1) {
            ncol = 2;
            co[0] = xi1;     cw[0] = wx2 - wx1;
            co[1] = xi1 + 1; cw[1] = wx1 - wx2;
            co[2] = 0; cw[2] = 0.f; co[3] = 0; cw[3] = 0.f;
        } else if (xi2 == xi1 + 1) {
            ncol = 3;
            co[0] = xi1;     cw[0] = 1.f - wx1;
            co[1] = xi1 + 1; cw[1] = wx1 - (1.f - wx2);
            co[2] = xi2 + 1; cw[2] = -wx2;
            co[3] = 0; cw[3] = 0.f;
        } else {
            ncol = 4;
            co[0] = xi1;     cw[0] = 1.f - wx1;
            co[1] = xi1 + 1; cw[1] = wx1;
            co[2] = xi2;     cw[2] = -(1.f - wx2);
            co[3] = xi2 + 1; cw[3] = -wx2;
        }
#pragma unroll
        for (int i = 0; i < 4; i++) {
            bool ok = (co[i] >= 0) && (co[i] < Wf);
            cw[i] = ok ? cw[i] : 0.f;
            co[i] = ok ? co[i] * 256 : 0;
        }
        float* dst = g_ctab + (size_t)idx * 12;
        dst[0] = cw[0]; dst[1] = cw[1]; dst[2] = cw[2]; dst[3] = cw[3];
        ((int*)dst)[4] = co[0]; ((int*)dst)[5] = co[1];
        ((int*)dst)[6] = co[2]; ((int*)dst)[7] = co[3];
        dst[8] = x2 - x1;
        ((int*)dst)[9] = ncol;
        dst[10] = 0.f; dst[11] = 0.f;
    } else {
        int idx = gidx - 5 * NCELL;
        if (idx >= 5 * NZ * ND) return;
        int d = idx % ND;
        int t = idx / ND;
        int z = t % NZ;
        int l = t / NZ;
        int Hf = c_HH[l], Wf = c_WW[l];

        float ya = projnc(P, z,     d,     0).y;
        float yb = projnc(P, z,     d + 1, 0).y;
        float yc = projnc(P, z + 1, d,     0).y;
        float yd = projnc(P, z + 1, d + 1, 0).y;
        float y1 = fminf(ya, yb);
        float y2 = fmaxf(yc, yd);

        float yp1 = (y1 + 1.f) * (Hf * 0.5f) - 0.5f;
        float yf1 = floorf(yp1); float wy1 = yp1 - yf1; int yi1 = (int)yf1;
        float yp2 = (y2 + 1.f) * (Hf * 0.5f) - 0.5f;
        float yf2 = floorf(yp2); float wy2 = yp2 - yf2; int yi2 = (int)yf2;

        float rw[4]; int ro[4]; int nrow;
        if (yi2 == yi1) {
            nrow = 2;
            ro[0] = yi1;     rw[0] = wy2 - wy1;
            ro[1] = yi1 + 1; rw[1] = wy1 - wy2;
            ro[2] = 0; rw[2] = 0.f; ro[3] = 0; rw[3] = 0.f;
        } else if (yi2 == yi1 + 1) {
            nrow = 3;
            ro[0] = yi1;     rw[0] = 1.f - wy1;
            ro[1] = yi1 + 1; rw[1] = wy1 - (1.f - wy2);
            ro[2] = yi2 + 1; rw[2] = -wy2;
            ro[3] = 0; rw[3] = 0.f;
        } else {
            nrow = 4;
            ro[0] = yi1;     rw[0] = 1.f - wy1;
            ro[1] = yi1 + 1; rw[1] = wy1;
            ro[2] = yi2;     rw[2] = -(1.f - wy2);
            ro[3] = yi2 + 1; rw[3] = -wy2;
        }
#pragma unroll
        for (int i = 0; i < 4; i++) {
            bool ok = (ro[i] >= 0) && (ro[i] < Hf);
            rw[i] = ok ? rw[i] : 0.f;
            ro[i] = ok ? ro[i] * Wf * 256 : 0;
        }
        float* dst = g_rtab + (size_t)idx * 12;
        dst[0] = rw[0]; dst[1] = rw[1]; dst[2] = rw[2]; dst[3] = rw[3];
        ((int*)dst)[4] = ro[0]; ((int*)dst)[5] = ro[1];
        ((int*)dst)[6] = ro[2]; ((int*)dst)[7] = ro[3];
        dst[8] = y2 - y1;
        ((int*)dst)[9] = nrow;
        dst[10] = 0.f; dst[11] = 0.f;
    }
}

// ---------------- merged weight permutes: wb (2949120) then w2p (589824) ----------------
__global__ void k_permw(const float* __restrict__ w, const float* __restrict__ w2) {
    int gidx = blockIdx.x * 256 + threadIdx.x;
    if (gidx < 5 * 256 * HC_) {
        int idx = gidx;
        int zo = idx % HC_;
        int t = idx / HC_;
        int c = t & 255;
        int l = t >> 8;
        int z = zo >> 8, o = zo & 255;
        g_wb[idx] = to_tf32(w[((size_t)(l * IMC_ + o)) * HC_ + c * 9 + z]);
    } else {
        int idx = gidx - 5 * 256 * HC_;
        if (idx >= IMC_ * 9 * IMC_) return;
        int o = idx & 255;
        int t = idx >> 8;
        int kk = t % 9;
        int cin = t / 9;
        g_w2p[idx] = to_tf32(w2[(o * IMC_ + cin) * 9 + kk]);
    }
}

// ---------------- tf32 tensor-core GEMM, 3-stage cp.async pipeline, 3 CTAs/SM ----------------
#define SPAD 136
#define STAGES 3
#define STAGEF (16 * SPAD)
__global__ __launch_bounds__(256, 3) void k_pgemm() {
    extern __shared__ float sm[];
    float* As = sm;                      // [STAGES][16*SPAD]
    float* Bs = sm + STAGES * STAGEF;    // [STAGES][16*SPAD]

    int bx = blockIdx.x;
    int l = 0;
    while (bx >= c_MTCUM[l + 1]) l++;
    int mtile = bx - c_MTCUM[l];
    int HW = c_HH[l] * c_WW[l];
    const float* __restrict__ Ag = g_fr + c_FOFF[l];
    const float* __restrict__ Bg = g_wb + (size_t)l * 256 * HC_;
    float* __restrict__ P = g_P + c_POFF[l];

    int tid = threadIdx.x;
    int m0 = mtile * 128;
    int n0 = blockIdx.y * 128;

    int lane = tid & 31;
    int g = lane >> 2, t = lane & 3;
    int wid = tid >> 5;
    int wm = (wid & 1) * 64;
    int wn = (wid >> 1) * 32;

    float acc[4][4][4];
#pragma unroll
    for (int i = 0; i < 4; i++)
#pragma unroll
        for (int j = 0; j < 4; j++)
#pragma unroll
            for (int q = 0; q < 4; q++) acc[i][j][q] = 0.f;

    int ka0 = tid >> 5, ma0 = (tid & 31) * 4;
    int ka1 = (tid + 256) >> 5;
    int gm = m0 + ma0;
    bool gmv = gm < HW;

    uint32_t asb = (uint32_t)__cvta_generic_to_shared(As);
    uint32_t bsb = (uint32_t)__cvta_generic_to_shared(Bs);
    uint32_t adst0 = asb + (uint32_t)(ka0 * SPAD + ma0) * 4;
    uint32_t adst1 = asb + (uint32_t)(ka1 * SPAD + ma0) * 4;
    uint32_t bdst0 = bsb + (uint32_t)(ka0 * SPAD + ma0) * 4;
    uint32_t bdst1 = bsb + (uint32_t)(ka1 * SPAD + ma0) * 4;
    const uint32_t sbytes = STAGEF * 4;

    const int NKT = 16;
#pragma unroll
    for (int s = 0; s < 2; s++) {
        int c0 = s * 16;
        cpa16(adst0 + s * sbytes, Ag + (size_t)(c0 + ka0) * HW + gm, gmv);
        cpa16(adst1 + s * sbytes, Ag + (size_t)(c0 + ka1) * HW + gm, gmv);
        cpa16(bdst0 + s * sbytes, Bg + (size_t)(c0 + ka0) * HC_ + n0 + ma0, true);
        cpa16(bdst1 + s * sbytes, Bg + (size_t)(c0 + ka1) * HC_ + n0 + ma0, true);
        CP_COMMIT();
    }

    int buf = 0;
    for (int kt = 0; kt < NKT; kt++) {
        CP_WAIT1();
        __syncthreads();
        if (kt + 2 < NKT) {
            int s = buf + 2; if (s >= 3) s -= 3;
            int c0 = (kt + 2) * 16;
            cpa16(adst0 + s * sbytes, Ag + (size_t)(c0 + ka0) * HW + gm, gmv);
            cpa16(adst1 + s * sbytes, Ag + (size_t)(c0 + ka1) * HW + gm, gmv);
            cpa16(bdst0 + s * sbytes, Bg + (size_t)(c0 + ka0) * HC_ + n0 + ma0, true);
            cpa16(bdst1 + s * sbytes, Bg + (size_t)(c0 + ka1) * HC_ + n0 + ma0, true);
        }
        CP_COMMIT();

        const float* Ab = As + buf * STAGEF;
        const float* Bb = Bs + buf * STAGEF;
#pragma unroll
        for (int ks = 0; ks < 2; ks++) {
            int kk = ks * 8;
            uint32_t af[4][4], bf[4][2];
#pragma unroll
            for (int mf = 0; mf < 4; mf++) {
                int m = wm + mf * 16 + g;
                af[mf][0] = __float_as_uint(Ab[(kk + t) * SPAD + m]);
                af[mf][1] = __float_as_uint(Ab[(kk + t) * SPAD + m + 8]);
                af[mf][2] = __float_as_uint(Ab[(kk + t + 4) * SPAD + m]);
                af[mf][3] = __float_as_uint(Ab[(kk + t + 4) * SPAD + m + 8]);
            }
#pragma unroll
            for (int nf = 0; nf < 4; nf++) {
                int n = wn + nf * 8 + g;
                bf[nf][0] = __float_as_uint(Bb[(kk + t) * SPAD + n]);
                bf[nf][1] = __float_as_uint(Bb[(kk + t + 4) * SPAD + n]);
            }
#pragma unroll
            for (int mf = 0; mf < 4; mf++)
#pragma unroll
                for (int nf = 0; nf < 4; nf++) {
                    asm volatile(
                        "mma.sync.aligned.m16n8k8.row.col.f32.tf32.tf32.f32 "
                        "{%0,%1,%2,%3}, {%4,%5,%6,%7}, {%8,%9}, {%0,%1,%2,%3};"
                        : "+f"(acc[mf][nf][0]), "+f"(acc[mf][nf][1]),
                          "+f"(acc[mf][nf][2]), "+f"(acc[mf][nf][3])
                        : "r"(af[mf][0]), "r"(af[mf][1]), "r"(af[mf][2]), "r"(af[mf][3]),
                          "r"(bf[nf][0]), "r"(bf[nf][1]));
                }
        }
        buf = (buf == 2) ? 0 : buf + 1;
    }

    int z = n0 >> 8;
    int ob0 = n0 & 255;
#pragma unroll
    for (int mf = 0; mf < 4; mf++) {
        int m = m0 + wm + mf * 16 + g;
#pragma unroll
        for (int nf = 0; nf < 4; nf++) {
            int o = ob0 + wn + nf * 8 + 2 * t;
            if (m < HW) {
                float* dst = P + ((size_t)z * HW + m) * 256 + o;
                *(float2*)dst = make_float2(acc[mf][nf][0], acc[mf][nf][1]);
            }
            if (m + 8 < HW) {
                float* dst = P + ((size_t)z * HW + m + 8) * 256 + o;
                *(float2*)dst = make_float2(acc[mf][nf][2], acc[mf][nf][3]);
            }
        }
    }
}

// ---------------- merged float4 cumsum of P along w (all levels) ----------------
__global__ void k_prow(void) {
    int t = blockIdx.x * 256 + threadIdx.x;
    if (t >= 107136) return;
    int l = 0;
    while (t >= c_RCUM4[l + 1]) l++;
    int tt = t - c_RCUM4[l];
    int H = c_HH[l], W = c_WW[l];
    int o4 = (tt & 63) * 4;
    int r = tt >> 6;
    int h = r % H, z = r / H;
    float* p = g_P + c_POFF[l] + ((size_t)(z * H + h) * W) * 256 + o4;
    float4 a = make_float4(0, 0, 0, 0);
    for (int w = 0; w < W; w += 4) {
        float4 v0 = *(float4*)(p + (w + 0) * 256);
        float4 v1 = *(float4*)(p + (w + 1) * 256);
        float4 v2 = *(float4*)(p + (w + 2) * 256);
        float4 v3 = *(float4*)(p + (w + 3) * 256);
        a.x += v0.x; a.y += v0.y; a.z += v0.z; a.w += v0.w;
        *(float4*)(p + (w + 0) * 256) = a;
        a.x += v1.x; a.y += v1.y; a.z += v1.z; a.w += v1.w;
        *(float4*)(p + (w + 1) * 256) = a;
        a.x += v2.x; a.y += v2.y; a.z += v2.z; a.w += v2.w;
        *(float4*)(p + (w + 2) * 256) = a;
        a.x += v3.x; a.y += v3.y; a.z += v3.z; a.w += v3.w;
        *(float4*)(p + (w + 3) * 256) = a;
    }
}

// ---------------- merged float4 cumsum of P along h (all levels), unroll 6 ----------------
__global__ void k_pcol(void) {
    int t = blockIdx.x * 256 + threadIdx.x;
    if (t >= 357120) return;
    int l = 0;
    while (t >= c_CCUM4[l + 1]) l++;
    int tt = t - c_CCUM4[l];
    int H = c_HH[l], W = c_WW[l];
    int o4 = (tt & 63) * 4;
    int r = tt >> 6;
    int w = r % W, z = r / W;
    float* p = g_P + c_POFF[l] + ((size_t)z * H * W + w) * 256 + o4;
    int stride = W * 256;
    float4 a = make_float4(0, 0, 0, 0);
    for (int h = 0; h < H; h += 6) {
        float4 v0 = *(float4*)(p + (h + 0) * stride);
        float4 v1 = *(float4*)(p + (h + 1) * stride);
        float4 v2 = *(float4*)(p + (h + 2) * stride);
        float4 v3 = *(float4*)(p + (h + 3) * stride);
        float4 v4 = *(float4*)(p + (h + 4) * stride);
        float4 v5 = *(float4*)(p + (h + 5) * stride);
        a.x += v0.x; a.y += v0.y; a.z += v0.z; a.w += v0.w;
        *(float4*)(p + (h + 0) * stride) = a;
        a.x += v1.x; a.y += v1.y; a.z += v1.z; a.w += v1.w;
        *(float4*)(p + (h + 1) * stride) = a;
        a.x += v2.x; a.y += v2.y; a.z += v2.z; a.w += v2.w;
        *(float4*)(p + (h + 2) * stride) = a;
        a.x += v3.x; a.y += v3.y; a.z += v3.z; a.w += v3.w;
        *(float4*)(p + (h + 3) * stride) = a;
        a.x += v4.x; a.y += v4.y; a.z += v4.z; a.w += v4.w;
        *(float4*)(p + (h + 4) * stride) = a;
        a.x += v5.x; a.y += v5.y; a.z += v5.z; a.w += v5.w;
        *(float4*)(p + (h + 5) * stride) = a;
    }
}

// ---------------- fused gather (dedup-table-driven, R7 structure) ----------------
__global__ __launch_bounds__(256) void k_gather(const float* __restrict__ bias) {
    int n = blockIdx.x;
    int l = blockIdx.y;
    int o = threadIdx.x;
    int Hf = c_HH[l], Wf = c_WW[l];
    int HW = Hf * Wf;
    float areaF = (float)HW * 0.25f;
    const float* __restrict__ P = g_P + c_POFF[l];
    int d = n / NWC;

    const float* ct = g_ctab + (size_t)(l * NCELL + n) * 12;
    float4 cw = *(const float4*)ct;
    int4 co = *(const int4*)(ct + 4);
    float xw = ct[8];
    int ncol = ((const int*)ct)[9];

    float acc = bias[l * 256 + o];

    const float* tab = g_rtab + (size_t)((l * NZ) * ND + d) * 12;
#pragma unroll
    for (int z = 0; z < NZ; z++, tab += ND * 12) {
        float4 rw = *(const float4*)tab;
        int4 ro = *(const int4*)(tab + 4);
        float yh = tab[8];
        int nrow = ((const int*)tab)[9];
        float area = xw * yh * areaF + 1e-6f;
        if (!(area > 1e-6f)) continue;
        float inv = 1.0f / area;
        const float* Pz = P + (size_t)z * HW * 256 + o;

        const float* Pr0 = Pz + ro.x;
        float rs0 = cw.x * Pr0[co.x] + cw.y * Pr0[co.y];
        if (ncol > 2) rs0 += cw.z * Pr0[co.z];
        if (ncol > 3) rs0 += cw.w * Pr0[co.w];
        const float* Pr1 = Pz + ro.y;
        float rs1 = cw.x * Pr1[co.x] + cw.y * Pr1[co.y];
        if (ncol > 2) rs1 += cw.z * Pr1[co.z];
        if (ncol > 3) rs1 += cw.w * Pr1[co.w];
        float s = rw.x * rs0 + rw.y * rs1;
        if (nrow > 2) {
            const float* Pr2 = Pz + ro.z;
            float rs2 = cw.x * Pr2[co.x] + cw.y * Pr2[co.y];
            if (ncol > 2) rs2 += cw.z * Pr2[co.z];
            if (ncol > 3) rs2 += cw.w * Pr2[co.w];
            s += rw.z * rs2;
        }
        if (nrow > 3) {
            const float* Pr3 = Pz + ro.w;
            float rs3 = cw.x * Pr3[co.x] + cw.y * Pr3[co.y];
            if (ncol > 2) rs3 += cw.z * Pr3[co.z];
            if (ncol > 3) rs3 += cw.w * Pr3[co.w];
            s += rw.w * rs3;
        }
        acc += inv * s;
    }
    int w = n - d * NWC;
    int sp = w * ND + d;
    g_xcat[(l * 256 + o) * NCELL + sp] = fmaxf(acc, 0.0f);
}

// ---------------- channel means (float4) ----------------
__global__ void k_colmean() {
    int g = blockIdx.x;
    const float4* p = (const float4*)(g_xcat + (size_t)g * NCELL);
    float s = 0.f;
    for (int i = threadIdx.x; i < NCELL / 4; i += 256) {
        float4 v = p[i];
        s += v.x + v.y + v.z + v.w;
    }
    __shared__ float sm[256];
    sm[threadIdx.x] = s;
    __syncthreads();
    for (int st = 128; st > 0; st >>= 1) {
        if (threadIdx.x < st) sm[threadIdx.x] += sm[threadIdx.x + st];
        __syncthreads();
    }
    if (threadIdx.x == 0) g_colmean[g] = sm[0] * (1.0f / (float)NCELL);
}

__global__ void k_att(const float* __restrict__ aw, const float* __restrict__ ab) {
    __shared__ float cm[IMC_];
    int l = blockIdx.x, o = threadIdx.x;
    cm[o] = g_colmean[l * IMC_ + o];
    __syncthreads();
    float acc = ab[o];
    for (int c = 0; c < IMC_; c++) acc += cm[c] * aw[o * IMC_ + c];
    g_sig[l * IMC_ + o] = 1.0f / (1.0f + expf(-acc));
}

// ---------------- fold attention + transpose conv1 weights -> tf32 [k][o] ----------------
__global__ void k_wscale(const float* __restrict__ w) {
    int idx = blockIdx.x * 256 + threadIdx.x;
    if (idx >= CATC * 9 * IMC_) return;
    int o = idx & 255;
    int t = idx >> 8;
    int kk = t % 9;
    int cin = t / 9;
    g_w1s[idx] = to_tf32(w[(o * CATC + cin) * 9 + kk] * g_sig[cin]);
}

// ---------------- implicit-GEMM tf32 conv (3x3, pad 1), split-K partials ----------------
#define APAD 68
#define BPAD 132
template<int STRIDE, int IH, int IW, int CONV1, int KCHUNK>
__global__ __launch_bounds__(256) void k_convmma() {
    const float* __restrict__ src = CONV1 ? g_xcat : g_y1;
    const float* __restrict__ wt  = CONV1 ? g_w1s : g_w2p;
    float* __restrict__ part = (CONV1 ? g_c1part : g_c2part) + (size_t)blockIdx.z * IMC_ * OSP;

    __shared__ float As[2][16 * APAD];
    __shared__ float Bs[2][16 * BPAD];

    int tid = threadIdx.x;
    int m0 = blockIdx.x * 64;
    int n0 = blockIdx.y * 128;
    int kbase = blockIdx.z * KCHUNK;

    int lane = tid & 31;
    int g = lane >> 2, t4 = lane & 3;
    int wid = tid >> 5;
    int wm = (wid & 1) * 32;
    int wn = (wid >> 1) * 32;

    int ma = tid & 63;
    int kqa = tid >> 6;
    int m = m0 + ma;
    bool mv = m < OSP;
    int mq = mv ? m : 0;
    int oh = mq / OW1, ow = mq - oh * OW1;
    int ihb = STRIDE * oh - 1, iwb = STRIDE * ow - 1;

    int nb = (tid & 31) * 4;
    int kqb = tid >> 5;

    float acc[2][4][4];
#pragma unroll
    for (int i = 0; i < 2; i++)
#pragma unroll
        for (int j = 0; j < 4; j++)
#pragma unroll
            for (int q = 0; q < 4; q++) acc[i][j][q] = 0.f;

    {
#pragma unroll
        for (int i = 0; i < 4; i++) {
            int kg = kbase + kqa * 4 + i;
            int cin = kg / 9; int r = kg - cin * 9;
            int ky = r / 3, kx = r - ky * 3;
            int ih = ihb + ky, iw = iwb + kx;
            bool ok = mv && ih >= 0 && ih < IH && iw >= 0 && iw < IW;
            float v = ok ? src[(size_t)cin * (IH * IW) + ih * IW + iw] : 0.f;
            As[0][(kqa * 4 + i) * APAD + ma] = to_tf32(v);
        }
#pragma unroll
        for (int p = 0; p < 2; p++) {
            int kk = kqb + p * 8;
            *(float4*)&Bs[0][kk * BPAD + nb] = *(const float4*)(wt + (size_t)(kbase + kk) * 256 + n0 + nb);
        }
    }
    __syncthreads();

    const int NT = KCHUNK / 16;
    for (int kt = 0; kt < NT; kt++) {
        int buf = kt & 1;
        float pa[4];
        float4 pb[2];
        if (kt + 1 < NT) {
            int k0n = kbase + (kt + 1) * 16;
#pragma unroll
            for (int i = 0; i < 4; i++) {
                int kg = k0n + kqa * 4 + i;
                int cin = kg / 9; int r = kg - cin * 9;
                int ky = r / 3, kx = r - ky * 3;
                int ih = ihb + ky, iw = iwb + kx;
                bool ok = mv && ih >= 0 && ih < IH && iw >= 0 && iw < IW;
                pa[i] = ok ? src[(size_t)cin * (IH * IW) + ih * IW + iw] : 0.f;
            }
#pragma unroll
            for (int p = 0; p < 2; p++) {
                int kk = kqb + p * 8;
                pb[p] = *(const float4*)(wt + (size_t)(k0n + kk) * 256 + n0 + nb);
            }
        }
#pragma unroll
        for (int ks = 0; ks < 2; ks++) {
            int kk = ks * 8;
            uint32_t af[2][4], bf[4][2];
#pragma unroll
            for (int mf = 0; mf < 2; mf++) {
                int mm = wm + mf * 16 + g;
                af[mf][0] = __float_as_uint(As[buf][(kk + t4) * APAD + mm]);
                af[mf][1] = __float_as_uint(As[buf][(kk + t4) * APAD + mm + 8]);
                af[mf][2] = __float_as_uint(As[buf][(kk + t4 + 4) * APAD + mm]);
                af[mf][3] = __float_as_uint(As[buf][(kk + t4 + 4) * APAD + mm + 8]);
            }
#pragma unroll
            for (int nf = 0; nf < 4; nf++) {
                int nn = wn + nf * 8 + g;
                bf[nf][0] = __float_as_uint(Bs[buf][(kk + t4) * BPAD + nn]);
                bf[nf][1] = __float_as_uint(Bs[buf][(kk + t4 + 4) * BPAD + nn]);
            }
#pragma unroll
            for (int mf = 0; mf < 2; mf++)
#pragma unroll
                for (int nf = 0; nf < 4; nf++) {
                    asm volatile(
                        "mma.sync.aligned.m16n8k8.row.col.f32.tf32.tf32.f32 "
                        "{%0,%1,%2,%3}, {%4,%5,%6,%7}, {%8,%9}, {%0,%1,%2,%3};"
                        : "+f"(acc[mf][nf][0]), "+f"(acc[mf][nf][1]),
                          "+f"(acc[mf][nf][2]), "+f"(acc[mf][nf][3])
                        : "r"(af[mf][0]), "r"(af[mf][1]), "r"(af[mf][2]), "r"(af[mf][3]),
                          "r"(bf[nf][0]), "r"(bf[nf][1]));
                }
        }
        if (kt + 1 < NT) {
            int b2 = buf ^ 1;
#pragma unroll
            for (int i = 0; i < 4; i++)
                As[b2][(kqa * 4 + i) * APAD + ma] = to_tf32(pa[i]);
#pragma unroll
            for (int p = 0; p < 2; p++)
                *(float4*)&Bs[b2][(kqb + p * 8) * BPAD + nb] = pb[p];
        }
        __syncthreads();
    }

#pragma unroll
    for (int mf = 0; mf < 2; mf++) {
        int mrow = m0 + wm + mf * 16 + g;
#pragma unroll
        for (int nf = 0; nf < 4; nf++) {
            int o = n0 + wn + nf * 8 + 2 * t4;
            if (mrow < OSP) {
                part[(size_t)o * OSP + mrow] = acc[mf][nf][0];
                part[(size_t)(o + 1) * OSP + mrow] = acc[mf][nf][1];
            }
            if (mrow + 8 < OSP) {
                part[(size_t)o * OSP + mrow + 8] = acc[mf][nf][2];
                part[(size_t)(o + 1) * OSP + mrow + 8] = acc[mf][nf][3];
            }
        }
    }
}

__global__ void k_c1red(const float* __restrict__ bg, const float* __restrict__ bb,
                        const float* __restrict__ bm, const float* __restrict__ bv) {
    int idx = blockIdx.x * 256 + threadIdx.x;
    if (idx >= IMC_ * OSP) return;
    int o = idx / OSP;
    float s = 0.f;
#pragma unroll
    for (int p = 0; p < 8; p++) s += g_c1part[(size_t)p * IMC_ * OSP + idx];
    float sc = bg[o] / sqrtf(bv[o] + 1e-5f);
    g_y1[idx] = fmaxf((s - bm[o]) * sc + bb[o], 0.f);
}

__global__ void k_c2red(const float* __restrict__ bg, const float* __restrict__ bb,
                        const float* __restrict__ bm, const float* __restrict__ bv,
                        float* __restrict__ out) {
    int idx = blockIdx.x * 256 + threadIdx.x;
    if (idx >= IMC_ * OSP) return;
    int o = idx / OSP;
    float s = 0.f;
#pragma unroll
    for (int p = 0; p < 4; p++) s += g_c2part[(size_t)p * IMC_ * OSP + idx];
    float sc = bg[o] / sqrtf(bv[o] + 1e-5f);
    out[idx] = fmaxf((s - bm[o]) * sc + bb[o], 0.f);
}

// ---------------- launch ----------------
extern "C" void kernel_launch(void* const* d_in, const int* in_sizes, int n_in,
                              void* d_out, int out_size) {
    (void)in_sizes; (void)n_in; (void)out_size;
    const float* f0 = (const float*)d_in[0];
    const float* f1 = (const float*)d_in[1];
    const float* f2 = (const float*)d_in[2];
    const float* f3 = (const float*)d_in[3];
    const float* f4 = (const float*)d_in[4];
    const float* calib = (const float*)d_in[5];
    const float* oftw  = (const float*)d_in[6];
    const float* oftb  = (const float*)d_in[7];
    const float* attw  = (const float*)d_in[8];
    const float* attb  = (const float*)d_in[9];
    const float* c1w   = (const float*)d_in[10];
    const float* b1g   = (const float*)d_in[11];
    const float* b1b   = (const float*)d_in[12];
    const float* b1m   = (const float*)d_in[13];
    const float* b1v   = (const float*)d_in[14];
    const float* c2w   = (const float*)d_in[15];
    const float* b2g   = (const float*)d_in[16];
    const float* b2b   = (const float*)d_in[17];
    const float* b2m   = (const float*)d_in[18];
    const float* b2v   = (const float*)d_in[19];
    float* out = (float*)d_out;

    k_round<<<(2618880 + 255) / 256, 256>>>(f0, f1, f2, f3, f4);
    k_tab<<<(5 * NCELL + 5 * NZ * ND + 255) / 256, 256>>>(calib);
    k_permw<<<(5 * 256 * HC_ + IMC_ * 9 * IMC_ + 255) / 256, 256>>>(oftw, c2w);

    const int pg_smem = STAGES * 2 * 16 * SPAD * 4;   // 52224 B
    cudaFuncSetAttribute(k_pgemm, cudaFuncAttributeMaxDynamicSharedMemorySize, pg_smem);
    k_pgemm<<<dim3(320, 18), 256, pg_smem>>>();

    k_prow<<<(107136 + 255) / 256, 256>>>();
    k_pcol<<<(357120 + 255) / 256, 256>>>();
    k_gather<<<dim3(NCELL, 5), 256>>>(oftb);

    k_colmean<<<CATC, 256>>>();
    k_att<<<5, 256>>>(attw, attb);
    k_wscale<<<(CATC * 9 * IMC_ + 255) / 256, 256>>>(c1w);

    // conv1: K = 1280*9 = 11520, split-K 8 (chunk 1440)
    k_convmma<2, NWC, ND, 1, 1440><<<dim3((OSP + 63) / 64, 2, 8), 256>>>();
    k_c1red<<<(IMC_ * OSP + 255) / 256, 256>>>(b1g, b1b, b1m, b1v);
    // conv2: K = 256*9 = 2304, split-K 4 (chunk 576)
    k_convmma<1, OH1, OW1, 0, 576><<<dim3((OSP + 63) / 64, 2, 4), 256>>>();
    k_c2red<<<(IMC_ * OSP + 255) / 256, 256>>>(b2g, b2b, b2m, b2v, out);
}

// round 15
// speedup vs baseline: 1.0631x; 1.0631x over previous
#include <cuda_runtime.h>
#include <cstdint>

// ---------------- problem constants ----------------
#define NZ 9
#define ND 108          // depth cells (conv W dim)
#define NWC 124         // width cells (conv H dim)
#define NCELL 13392     // ND*NWC
#define IMC_ 256
#define HC_ 2304        // 9*256
#define CATC 1280
#define OH1 62
#define OW1 54
#define OSP 3348        // 62*54

// level geometry
__device__ __constant__ int c_HH[5] = { 96, 48, 24, 12, 6 };
__device__ __constant__ int c_WW[5] = { 320, 160, 80, 40, 20 };
// float-offsets of per-level P buffers (HW*2304)
__device__ __constant__ int c_POFF[5]  = { 0, 70778880, 88473600, 92897280, 94003200 };
// float-offsets of per-level rounded-feat buffers (HW*256)
__device__ __constant__ int c_FOFF[5]  = { 0, 7864320, 9830400, 10321920, 10444800 };
// cumulative float4 counts for merged k_round
__device__ __constant__ int c_FR4[6] = { 0, 1966080, 2457600, 2580480, 2611200, 2618880 };
// cumulative M-tile (128) counts per level for the fused GEMM
__device__ __constant__ int c_MTCUM[6] = { 0, 240, 300, 315, 319, 320 };
// cumulative thread counts for merged float4 cumsum kernels
__device__ __constant__ int c_RCUM4[6] = { 0, 55296, 82944, 96768, 103680, 107136 };
__device__ __constant__ int c_CCUM4[6] = { 0, 184320, 276480, 322560, 345600, 357120 };

// ---------------- scratch (device globals; no allocs allowed) ----------------
__device__ __align__(16) float g_P[94279680];       // all 5 levels, [z][hw][256] projected maps -> integral
__device__ __align__(16) float g_fr[10475520];      // tf32-rounded feats, all levels [c][hw]
__device__ __align__(16) float g_ctab[5 * NCELL * 12];    // col-tap table per (l,n)
__device__ __align__(16) float g_rtab[5 * NZ * ND * 12];  // row-tap table per (l,z,d)
__device__ __align__(16) float g_wb[5 * 256 * HC_];   // [l][c][z*256+o] tf32-rounded weights
__device__ __align__(16) float g_xcat[CATC * NCELL];  // concat ortho [1280][124][108]
__device__ __align__(16) float g_w1s[CATC * 9 * IMC_];
__device__ __align__(16) float g_w2p[IMC_ * 9 * IMC_];
__device__ float g_colmean[CATC];
__device__ float g_sig[CATC];
__device__ __align__(16) float g_y1[IMC_ * OSP];
__device__ __align__(16) float g_c1part[8 * IMC_ * OSP];
__device__ __align__(16) float g_c2part[4 * IMC_ * OSP];

__device__ __forceinline__ float to_tf32(float x) {
    float r;
    asm("cvt.rna.tf32.f32 %0, %1;" : "=f"(r) : "f"(x));
    return r;
}

__device__ __forceinline__ void cpa16(uint32_t dst, const float* src, bool pred) {
    asm volatile("cp.async.cg.shared.global [%0], [%1], 16, %2;"
                 :: "r"(dst), "l"(src), "r"(pred ? 16 : 0));
}
#define CP_COMMIT() asm volatile("cp.async.commit_group;" ::: "memory")
#define CP_WAIT1()  asm volatile("cp.async.wait_group 1;" ::: "memory")

// ---------------- corner projection (normalized, clamped) ----------------
__device__ __forceinline__ float2 projnc(const float* __restrict__ P, int zi, int di, int wi) {
    float X = 0.64f * (float)di;
    float Y = 39.68f - 0.64f * (float)wi;
    float Z = 2.76f - 0.64f * (float)zi;
    float hx = P[0] * X + P[1] * Y + P[2]  * Z + P[3];
    float hy = P[4] * X + P[5] * Y + P[6]  * Z + P[7];
    float hz = P[8] * X + P[9] * Y + P[10] * Z + P[11];
    float ix = hx / hz, iy = hy / hz;
    float nx = fminf(fmaxf(2.0f * ix / 1280.0f - 1.0f, -1.0f), 1.0f);
    float ny = fminf(fmaxf(2.0f * iy / 384.0f  - 1.0f, -1.0f), 1.0f);
    return make_float2(nx, ny);
}

// ---------------- merged: pre-round all feats to tf32 ----------------
__global__ void k_round(const float* __restrict__ f0, const float* __restrict__ f1,
                        const float* __restrict__ f2, const float* __restrict__ f3,
                        const float* __restrict__ f4) {
    int i = blockIdx.x * 256 + threadIdx.x;
    if (i >= 2618880) return;
    int l = 0;
    while (i >= c_FR4[l + 1]) l++;
    int ii = i - c_FR4[l];
    const float* f = (l == 0) ? f0 : (l == 1) ? f1 : (l == 2) ? f2 : (l == 3) ? f3 : f4;
    float4 v = ((const float4*)f)[ii];
    v.x = to_tf32(v.x); v.y = to_tf32(v.y); v.z = to_tf32(v.z); v.w = to_tf32(v.w);
    ((float4*)(g_fr + c_FOFF[l]))[ii] = v;
}

// ---------------- merged tap tables: ctab (5*NCELL) then rtab (5*NZ*ND) ----------------
__global__ void k_tab(const float* __restrict__ P) {
    int gidx = blockIdx.x * 256 + threadIdx.x;
    if (gidx < 5 * NCELL) {
        int idx = gidx;
        int n = idx % NCELL;
        int l = idx / NCELL;
        int d = n / NWC, w = n - d * NWC;
        int Wf = c_WW[l];

        float xa = projnc(P, 0, d,     w).x;
        float xb = projnc(P, 0, d + 1, w).x;
        float xc = projnc(P, 0, d + 1, w + 1).x;
        float xd = projnc(P, 0, d,     w + 1).x;
        float x1 = fminf(xa, xb);
        float x2 = fmaxf(xc, xd);

        float xp1 = (x1 + 1.f) * (Wf * 0.5f) - 0.5f;
        float xf1 = floorf(xp1); float wx1 = xp1 - xf1; int xi1 = (int)xf1;
        float xp2 = (x2 + 1.f) * (Wf * 0.5f) - 0.5f;
        float xf2 = floorf(xp2); float wx2 = xp2 - xf2; int xi2 = (int)xf2;

        float cw[4]; int co[4]; int ncol;
        if (xi2 == xi1) {
            ncol = 2;
            co[0] = xi1;     cw[0] = wx2 - wx1;
            co[1] = xi1 + 1; cw[1] = wx1 - wx2;
            co[2] = 0; cw[2] = 0.f; co[3] = 0; cw[3] = 0.f;
        } else if (xi2 == xi1 + 1) {
            ncol = 3;
            co[0] = xi1;     cw[0] = 1.f - wx1;
            co[1] = xi1 + 1; cw[1] = wx1 - (1.f - wx2);
            co[2] = xi2 + 1; cw[2] = -wx2;
            co[3] = 0; cw[3] = 0.f;
        } else {
            ncol = 4;
            co[0] = xi1;     cw[0] = 1.f - wx1;
            co[1] = xi1 + 1; cw[1] = wx1;
            co[2] = xi2;     cw[2] = -(1.f - wx2);
            co[3] = xi2 + 1; cw[3] = -wx2;
        }
#pragma unroll
        for (int i = 0; i < 4; i++) {
            bool ok = (co[i] >= 0) && (co[i] < Wf);
            cw[i] = ok ? cw[i] : 0.f;
            co[i] = ok ? co[i] * 256 : 0;
        }
        float* dst = g_ctab + (size_t)idx * 12;
        dst[0] = cw[0]; dst[1] = cw[1]; dst[2] = cw[2]; dst[3] = cw[3];
        ((int*)dst)[4] = co[0]; ((int*)dst)[5] = co[1];
        ((int*)dst)[6] = co[2]; ((int*)dst)[7] = co[3];
        dst[8] = x2 - x1;
        ((int*)dst)[9] = ncol;
        dst[10] = 0.f; dst[11] = 0.f;
    } else {
        int idx = gidx - 5 * NCELL;
        if (idx >= 5 * NZ * ND) return;
        int d = idx % ND;
        int t = idx / ND;
        int z = t % NZ;
        int l = t / NZ;
        int Hf = c_HH[l], Wf = c_WW[l];

        float ya = projnc(P, z,     d,     0).y;
        float yb = projnc(P, z,     d + 1, 0).y;
        float yc = projnc(P, z + 1, d,     0).y;
        float yd = projnc(P, z + 1, d + 1, 0).y;
        float y1 = fminf(ya, yb);
        float y2 = fmaxf(yc, yd);

        float yp1 = (y1 + 1.f) * (Hf * 0.5f) - 0.5f;
        float yf1 = floorf(yp1); float wy1 = yp1 - yf1; int yi1 = (int)yf1;
        float yp2 = (y2 + 1.f) * (Hf * 0.5f) - 0.5f;
        float yf2 = floorf(yp2); float wy2 = yp2 - yf2; int yi2 = (int)yf2;

        float rw[4]; int ro[4]; int nrow;
        if (yi2 == yi1) {
            nrow = 2;
            ro[0] = yi1;     rw[0] = wy2 - wy1;
            ro[1] = yi1 + 1; rw[1] = wy1 - wy2;
            ro[2] = 0; rw[2] = 0.f; ro[3] = 0; rw[3] = 0.f;
        } else if (yi2 == yi1 + 1) {
            nrow = 3;
            ro[0] = yi1;     rw[0] = 1.f - wy1;
            ro[1] = yi1 + 1; rw[1] = wy1 - (1.f - wy2);
            ro[2] = yi2 + 1; rw[2] = -wy2;
            ro[3] = 0; rw[3] = 0.f;
        } else {
            nrow = 4;
            ro[0] = yi1;     rw[0] = 1.f - wy1;
            ro[1] = yi1 + 1; rw[1] = wy1;
            ro[2] = yi2;     rw[2] = -(1.f - wy2);
            ro[3] = yi2 + 1; rw[3] = -wy2;
        }
#pragma unroll
        for (int i = 0; i < 4; i++) {
            bool ok = (ro[i] >= 0) && (ro[i] < Hf);
            rw[i] = ok ? rw[i] : 0.f;
            ro[i] = ok ? ro[i] * Wf * 256 : 0;
        }
        float* dst = g_rtab + (size_t)idx * 12;
        dst[0] = rw[0]; dst[1] = rw[1]; dst[2] = rw[2]; dst[3] = rw[3];
        ((int*)dst)[4] = ro[0]; ((int*)dst)[5] = ro[1];
        ((int*)dst)[6] = ro[2]; ((int*)dst)[7] = ro[3];
        dst[8] = y2 - y1;
        ((int*)dst)[9] = nrow;
        dst[10] = 0.f; dst[11] = 0.f;
    }
}

// ---------------- merged weight permutes: wb (2949120) then w2p (589824) ----------------
__global__ void k_permw(const float* __restrict__ w, const float* __restrict__ w2) {
    int gidx = blockIdx.x * 256 + threadIdx.x;
    if (gidx < 5 * 256 * HC_) {
        int idx = gidx;
        int zo = idx % HC_;
        int t = idx / HC_;
        int c = t & 255;
        int l = t >> 8;
        int z = zo >> 8, o = zo & 255;
        g_wb[idx] = to_tf32(w[((size_t)(l * IMC_ + o)) * HC_ + c * 9 + z]);
    } else {
        int idx = gidx - 5 * 256 * HC_;
        if (idx >= IMC_ * 9 * IMC_) return;
        int o = idx & 255;
        int t = idx >> 8;
        int kk = t % 9;
        int cin = t / 9;
        g_w2p[idx] = to_tf32(w2[(o * IMC_ + cin) * 9 + kk]);
    }
}

// ---------------- tf32 tensor-core GEMM, 3-stage cp.async pipeline (R13 config) ----------------
#define SPAD 136
#define STAGES 3
#define STAGEF (16 * SPAD)
__global__ __launch_bounds__(256) void k_pgemm() {
    extern __shared__ float sm[];
    float* As = sm;                      // [STAGES][16*SPAD]
    float* Bs = sm + STAGES * STAGEF;    // [STAGES][16*SPAD]

    int bx = blockIdx.x;
    int l = 0;
    while (bx >= c_MTCUM[l + 1]) l++;
    int mtile = bx - c_MTCUM[l];
    int HW = c_HH[l] * c_WW[l];
    const float* __restrict__ Ag = g_fr + c_FOFF[l];
    const float* __restrict__ Bg = g_wb + (size_t)l * 256 * HC_;
    float* __restrict__ P = g_P + c_POFF[l];

    int tid = threadIdx.x;
    int m0 = mtile * 128;
    int n0 = blockIdx.y * 128;

    int lane = tid & 31;
    int g = lane >> 2, t = lane & 3;
    int wid = tid >> 5;
    int wm = (wid & 1) * 64;
    int wn = (wid >> 1) * 32;

    float acc[4][4][4];
#pragma unroll
    for (int i = 0; i < 4; i++)
#pragma unroll
        for (int j = 0; j < 4; j++)
#pragma unroll
            for (int q = 0; q < 4; q++) acc[i][j][q] = 0.f;

    int ka0 = tid >> 5, ma0 = (tid & 31) * 4;
    int ka1 = (tid + 256) >> 5;
    int gm = m0 + ma0;
    bool gmv = gm < HW;

    uint32_t asb = (uint32_t)__cvta_generic_to_shared(As);
    uint32_t bsb = (uint32_t)__cvta_generic_to_shared(Bs);
    uint32_t adst0 = asb + (uint32_t)(ka0 * SPAD + ma0) * 4;
    uint32_t adst1 = asb + (uint32_t)(ka1 * SPAD + ma0) * 4;
    uint32_t bdst0 = bsb + (uint32_t)(ka0 * SPAD + ma0) * 4;
    uint32_t bdst1 = bsb + (uint32_t)(ka1 * SPAD + ma0) * 4;
    const uint32_t sbytes = STAGEF * 4;

    const int NKT = 16;
#pragma unroll
    for (int s = 0; s < 2; s++) {
        int c0 = s * 16;
        cpa16(adst0 + s * sbytes, Ag + (size_t)(c0 + ka0) * HW + gm, gmv);
        cpa16(adst1 + s * sbytes, Ag + (size_t)(c0 + ka1) * HW + gm, gmv);
        cpa16(bdst0 + s * sbytes, Bg + (size_t)(c0 + ka0) * HC_ + n0 + ma0, true);
        cpa16(bdst1 + s * sbytes, Bg + (size_t)(c0 + ka1) * HC_ + n0 + ma0, true);
        CP_COMMIT();
    }

    int buf = 0;
    for (int kt = 0; kt < NKT; kt++) {
        CP_WAIT1();
        __syncthreads();
        if (kt + 2 < NKT) {
            int s = buf + 2; if (s >= 3) s -= 3;
            int c0 = (kt + 2) * 16;
            cpa16(adst0 + s * sbytes, Ag + (size_t)(c0 + ka0) * HW + gm, gmv);
            cpa16(adst1 + s * sbytes, Ag + (size_t)(c0 + ka1) * HW + gm, gmv);
            cpa16(bdst0 + s * sbytes, Bg + (size_t)(c0 + ka0) * HC_ + n0 + ma0, true);
            cpa16(bdst1 + s * sbytes, Bg + (size_t)(c0 + ka1) * HC_ + n0 + ma0, true);
        }
        CP_COMMIT();

        const float* Ab = As + buf * STAGEF;
        const float* Bb = Bs + buf * STAGEF;
#pragma unroll
        for (int ks = 0; ks < 2; ks++) {
            int kk = ks * 8;
            uint32_t af[4][4], bf[4][2];
#pragma unroll
            for (int mf = 0; mf < 4; mf++) {
                int m = wm + mf * 16 + g;
                af[mf][0] = __float_as_uint(Ab[(kk + t) * SPAD + m]);
                af[mf][1] = __float_as_uint(Ab[(kk + t) * SPAD + m + 8]);
                af[mf][2] = __float_as_uint(Ab[(kk + t + 4) * SPAD + m]);
                af[mf][3] = __float_as_uint(Ab[(kk + t + 4) * SPAD + m + 8]);
            }
#pragma unroll
            for (int nf = 0; nf < 4; nf++) {
                int n = wn + nf * 8 + g;
                bf[nf][0] = __float_as_uint(Bb[(kk + t) * SPAD + n]);
                bf[nf][1] = __float_as_uint(Bb[(kk + t + 4) * SPAD + n]);
            }
#pragma unroll
            for (int mf = 0; mf < 4; mf++)
#pragma unroll
                for (int nf = 0; nf < 4; nf++) {
                    asm volatile(
                        "mma.sync.aligned.m16n8k8.row.col.f32.tf32.tf32.f32 "
                        "{%0,%1,%2,%3}, {%4,%5,%6,%7}, {%8,%9}, {%0,%1,%2,%3};"
                        : "+f"(acc[mf][nf][0]), "+f"(acc[mf][nf][1]),
                          "+f"(acc[mf][nf][2]), "+f"(acc[mf][nf][3])
                        : "r"(af[mf][0]), "r"(af[mf][1]), "r"(af[mf][2]), "r"(af[mf][3]),
                          "r"(bf[nf][0]), "r"(bf[nf][1]));
                }
        }
        buf = (buf == 2) ? 0 : buf + 1;
    }

    int z = n0 >> 8;
    int ob0 = n0 & 255;
#pragma unroll
    for (int mf = 0; mf < 4; mf++) {
        int m = m0 + wm + mf * 16 + g;
#pragma unroll
        for (int nf = 0; nf < 4; nf++) {
            int o = ob0 + wn + nf * 8 + 2 * t;
            if (m < HW) {
                float* dst = P + ((size_t)z * HW + m) * 256 + o;
                *(float2*)dst = make_float2(acc[mf][nf][0], acc[mf][nf][1]);
            }
            if (m + 8 < HW) {
                float* dst = P + ((size_t)z * HW + m + 8) * 256 + o;
                *(float2*)dst = make_float2(acc[mf][nf][2], acc[mf][nf][3]);
            }
        }
    }
}

// ---------------- merged float4 cumsum of P along w (all levels) ----------------
__global__ void k_prow(void) {
    int t = blockIdx.x * 256 + threadIdx.x;
    if (t >= 107136) return;
    int l = 0;
    while (t >= c_RCUM4[l + 1]) l++;
    int tt = t - c_RCUM4[l];
    int H = c_HH[l], W = c_WW[l];
    int o4 = (tt & 63) * 4;
    int r = tt >> 6;
    int h = r % H, z = r / H;
    float* p = g_P + c_POFF[l] + ((size_t)(z * H + h) * W) * 256 + o4;
    float4 a = make_float4(0, 0, 0, 0);
    for (int w = 0; w < W; w += 4) {
        float4 v0 = *(float4*)(p + (w + 0) * 256);
        float4 v1 = *(float4*)(p + (w + 1) * 256);
        float4 v2 = *(float4*)(p + (w + 2) * 256);
        float4 v3 = *(float4*)(p + (w + 3) * 256);
        a.x += v0.x; a.y += v0.y; a.z += v0.z; a.w += v0.w;
        *(float4*)(p + (w + 0) * 256) = a;
        a.x += v1.x; a.y += v1.y; a.z += v1.z; a.w += v1.w;
        *(float4*)(p + (w + 1) * 256) = a;
        a.x += v2.x; a.y += v2.y; a.z += v2.z; a.w += v2.w;
        *(float4*)(p + (w + 2) * 256) = a;
        a.x += v3.x; a.y += v3.y; a.z += v3.z; a.w += v3.w;
        *(float4*)(p + (w + 3) * 256) = a;
    }
}

// ---------------- merged float4 cumsum of P along h (all levels), unroll 6 ----------------
__global__ void k_pcol(void) {
    int t = blockIdx.x * 256 + threadIdx.x;
    if (t >= 357120) return;
    int l = 0;
    while (t >= c_CCUM4[l + 1]) l++;
    int tt = t - c_CCUM4[l];
    int H = c_HH[l], W = c_WW[l];
    int o4 = (tt & 63) * 4;
    int r = tt >> 6;
    int w = r % W, z = r / W;
    float* p = g_P + c_POFF[l] + ((size_t)z * H * W + w) * 256 + o4;
    int stride = W * 256;
    float4 a = make_float4(0, 0, 0, 0);
    for (int h = 0; h < H; h += 6) {
        float4 v0 = *(float4*)(p + (h + 0) * stride);
        float4 v1 = *(float4*)(p + (h + 1) * stride);
        float4 v2 = *(float4*)(p + (h + 2) * stride);
        float4 v3 = *(float4*)(p + (h + 3) * stride);
        float4 v4 = *(float4*)(p + (h + 4) * stride);
        float4 v5 = *(float4*)(p + (h + 5) * stride);
        a.x += v0.x; a.y += v0.y; a.z += v0.z; a.w += v0.w;
        *(float4*)(p + (h + 0) * stride) = a;
        a.x += v1.x; a.y += v1.y; a.z += v1.z; a.w += v1.w;
        *(float4*)(p + (h + 1) * stride) = a;
        a.x += v2.x; a.y += v2.y; a.z += v2.z; a.w += v2.w;
        *(float4*)(p + (h + 2) * stride) = a;
        a.x += v3.x; a.y += v3.y; a.z += v3.z; a.w += v3.w;
        *(float4*)(p + (h + 3) * stride) = a;
        a.x += v4.x; a.y += v4.y; a.z += v4.z; a.w += v4.w;
        *(float4*)(p + (h + 4) * stride) = a;
        a.x += v5.x; a.y += v5.y; a.z += v5.z; a.w += v5.w;
        *(float4*)(p + (h + 5) * stride) = a;
    }
}

// ---------------- paired-cell gather: cells (2k, 2k+1) share d -> shared rtab/z-loop ----------------
__global__ __launch_bounds__(256) void k_gather(const float* __restrict__ bias) {
    int n0 = blockIdx.x * 2;
    int n1 = n0 + 1;
    int l = blockIdx.y;
    int o = threadIdx.x;
    int Hf = c_HH[l], Wf = c_WW[l];
    int HW = Hf * Wf;
    float areaF = (float)HW * 0.25f;
    const float* __restrict__ P = g_P + c_POFF[l];
    int d = n0 / NWC;   // same for n1 (NWC even)

    const float* ct0 = g_ctab + (size_t)(l * NCELL + n0) * 12;
    float4 cw0 = *(const float4*)ct0;
    int4 co0 = *(const int4*)(ct0 + 4);
    float xw0 = ct0[8];
    int ncol0 = ((const int*)ct0)[9];

    const float* ct1 = g_ctab + (size_t)(l * NCELL + n1) * 12;
    float4 cw1 = *(const float4*)ct1;
    int4 co1 = *(const int4*)(ct1 + 4);
    float xw1 = ct1[8];
    int ncol1 = ((const int*)ct1)[9];

    float bb = bias[l * 256 + o];
    float acc0 = bb, acc1 = bb;

    const float* tab = g_rtab + (size_t)((l * NZ) * ND + d) * 12;
#pragma unroll
    for (int z = 0; z < NZ; z++, tab += ND * 12) {
        float4 rw = *(const float4*)tab;
        int4 ro = *(const int4*)(tab + 4);
        float yh = tab[8];
        int nrow = ((const int*)tab)[9];
        float area0 = xw0 * yh * areaF + 1e-6f;
        float area1 = xw1 * yh * areaF + 1e-6f;
        bool v0 = area0 > 1e-6f;
        bool v1 = area1 > 1e-6f;
        if (!v0 && !v1) continue;
        float inv0 = v0 ? (1.0f / area0) : 0.f;
        float inv1 = v1 ? (1.0f / area1) : 0.f;
        const float* Pz = P + (size_t)z * HW * 256 + o;

        float s0 = 0.f, s1 = 0.f;
#pragma unroll
        for (int r = 0; r < 4; r++) {
            if (r >= nrow) break;
            int roff = (r == 0) ? ro.x : (r == 1) ? ro.y : (r == 2) ? ro.z : ro.w;
            float rwv = (r == 0) ? rw.x : (r == 1) ? rw.y : (r == 2) ? rw.z : rw.w;
            const float* Pr = Pz + roff;
            float rs0 = cw0.x * Pr[co0.x] + cw0.y * Pr[co0.y];
            if (ncol0 > 2) rs0 += cw0.z * Pr[co0.z];
            if (ncol0 > 3) rs0 += cw0.w * Pr[co0.w];
            float rs1 = cw1.x * Pr[co1.x] + cw1.y * Pr[co1.y];
            if (ncol1 > 2) rs1 += cw1.z * Pr[co1.z];
            if (ncol1 > 3) rs1 += cw1.w * Pr[co1.w];
            s0 += rwv * rs0;
            s1 += rwv * rs1;
        }
        acc0 += inv0 * s0;
        acc1 += inv1 * s1;
    }
    int w0 = n0 - d * NWC;
    int base = (l * 256 + o) * NCELL + w0 * ND + d;
    g_xcat[base] = fmaxf(acc0, 0.0f);
    g_xcat[base + ND] = fmaxf(acc1, 0.0f);   // w1 = w0+1 -> +ND in [w][d] layout
}

// ---------------- channel means (float4) ----------------
__global__ void k_colmean() {
    int g = blockIdx.x;
    const float4* p = (const float4*)(g_xcat + (size_t)g * NCELL);
    float s = 0.f;
    for (int i = threadIdx.x; i < NCELL / 4; i += 256) {
        float4 v = p[i];
        s += v.x + v.y + v.z + v.w;
    }
    __shared__ float sm[256];
    sm[threadIdx.x] = s;
    __syncthreads();
    for (int st = 128; st > 0; st >>= 1) {
        if (threadIdx.x < st) sm[threadIdx.x] += sm[threadIdx.x + st];
        __syncthreads();
    }
    if (threadIdx.x == 0) g_colmean[g] = sm[0] * (1.0f / (float)NCELL);
}

__global__ void k_att(const float* __restrict__ aw, const float* __restrict__ ab) {
    __shared__ float cm[IMC_];
    int l = blockIdx.x, o = threadIdx.x;
    cm[o] = g_colmean[l * IMC_ + o];
    __syncthreads();
    float acc = ab[o];
    for (int c = 0; c < IMC_; c++) acc += cm[c] * aw[o * IMC_ + c];
    g_sig[l * IMC_ + o] = 1.0f / (1.0f + expf(-acc));
}

// ---------------- fold attention + transpose conv1 weights -> tf32 [k][o] ----------------
__global__ void k_wscale(const float* __restrict__ w) {
    int idx = blockIdx.x * 256 + threadIdx.x;
    if (idx >= CATC * 9 * IMC_) return;
    int o = idx & 255;
    int t = idx >> 8;
    int kk = t % 9;
    int cin = t / 9;
    g_w1s[idx] = to_tf32(w[(o * CATC + cin) * 9 + kk] * g_sig[cin]);
}

// ---------------- implicit-GEMM tf32 conv (3x3, pad 1), split-K partials ----------------
#define APAD 68
#define BPAD 132
template<int STRIDE, int IH, int IW, int CONV1, int KCHUNK>
__global__ __launch_bounds__(256) void k_convmma() {
    const float* __restrict__ src = CONV1 ? g_xcat : g_y1;
    const float* __restrict__ wt  = CONV1 ? g_w1s : g_w2p;
    float* __restrict__ part = (CONV1 ? g_c1part : g_c2part) + (size_t)blockIdx.z * IMC_ * OSP;

    __shared__ float As[2][16 * APAD];
    __shared__ float Bs[2][16 * BPAD];

    int tid = threadIdx.x;
    int m0 = blockIdx.x * 64;
    int n0 = blockIdx.y * 128;
    int kbase = blockIdx.z * KCHUNK;

    int lane = tid & 31;
    int g = lane >> 2, t4 = lane & 3;
    int wid = tid >> 5;
    int wm = (wid & 1) * 32;
    int wn = (wid >> 1) * 32;

    int ma = tid & 63;
    int kqa = tid >> 6;
    int m = m0 + ma;
    bool mv = m < OSP;
    int mq = mv ? m : 0;
    int oh = mq / OW1, ow = mq - oh * OW1;
    int ihb = STRIDE * oh - 1, iwb = STRIDE * ow - 1;

    int nb = (tid & 31) * 4;
    int kqb = tid >> 5;

    float acc[2][4][4];
#pragma unroll
    for (int i = 0; i < 2; i++)
#pragma unroll
        for (int j = 0; j < 4; j++)
#pragma unroll
            for (int q = 0; q < 4; q++) acc[i][j][q] = 0.f;

    {
#pragma unroll
        for (int i = 0; i < 4; i++) {
            int kg = kbase + kqa * 4 + i;
            int cin = kg / 9; int r = kg - cin * 9;
            int ky = r / 3, kx = r - ky * 3;
            int ih = ihb + ky, iw = iwb + kx;
            bool ok = mv && ih >= 0 && ih < IH && iw >= 0 && iw < IW;
            float v = ok ? src[(size_t)cin * (IH * IW) + ih * IW + iw] : 0.f;
            As[0][(kqa * 4 + i) * APAD + ma] = to_tf32(v);
        }
#pragma unroll
        for (int p = 0; p < 2; p++) {
            int kk = kqb + p * 8;
            *(float4*)&Bs[0][kk * BPAD + nb] = *(const float4*)(wt + (size_t)(kbase + kk) * 256 + n0 + nb);
        }
    }
    __syncthreads();

    const int NT = KCHUNK / 16;
    for (int kt = 0; kt < NT; kt++) {
        int buf = kt & 1;
        float pa[4];
        float4 pb[2];
        if (kt + 1 < NT) {
            int k0n = kbase + (kt + 1) * 16;
#pragma unroll
            for (int i = 0; i < 4; i++) {
                int kg = k0n + kqa * 4 + i;
                int cin = kg / 9; int r = kg - cin * 9;
                int ky = r / 3, kx = r - ky * 3;
                int ih = ihb + ky, iw = iwb + kx;
                bool ok = mv && ih >= 0 && ih < IH && iw >= 0 && iw < IW;
                pa[i] = ok ? src[(size_t)cin * (IH * IW) + ih * IW + iw] : 0.f;
            }
#pragma unroll
            for (int p = 0; p < 2; p++) {
                int kk = kqb + p * 8;
                pb[p] = *(const float4*)(wt + (size_t)(k0n + kk) * 256 + n0 + nb);
            }
        }
#pragma unroll
        for (int ks = 0; ks < 2; ks++) {
            int kk = ks * 8;
            uint32_t af[2][4], bf[4][2];
#pragma unroll
            for (int mf = 0; mf < 2; mf++) {
                int mm = wm + mf * 16 + g;
                af[mf][0] = __float_as_uint(As[buf][(kk + t4) * APAD + mm]);
                af[mf][1] = __float_as_uint(As[buf][(kk + t4) * APAD + mm + 8]);
                af[mf][2] = __float_as_uint(As[buf][(kk + t4 + 4) * APAD + mm]);
                af[mf][3] = __float_as_uint(As[buf][(kk + t4 + 4) * APAD + mm + 8]);
            }
#pragma unroll
            for (int nf = 0; nf < 4; nf++) {
                int nn = wn + nf * 8 + g;
                bf[nf][0] = __float_as_uint(Bs[buf][(kk + t4) * BPAD + nn]);
                bf[nf][1] = __float_as_uint(Bs[buf][(kk + t4 + 4) * BPAD + nn]);
            }
#pragma unroll
            for (int mf = 0; mf < 2; mf++)
#pragma unroll
                for (int nf = 0; nf < 4; nf++) {
                    asm volatile(
                        "mma.sync.aligned.m16n8k8.row.col.f32.tf32.tf32.f32 "
                        "{%0,%1,%2,%3}, {%4,%5,%6,%7}, {%8,%9}, {%0,%1,%2,%3};"
                        : "+f"(acc[mf][nf][0]), "+f"(acc[mf][nf][1]),
                          "+f"(acc[mf][nf][2]), "+f"(acc[mf][nf][3])
                        : "r"(af[mf][0]), "r"(af[mf][1]), "r"(af[mf][2]), "r"(af[mf][3]),
                          "r"(bf[nf][0]), "r"(bf[nf][1]));
                }
        }
        if (kt + 1 < NT) {
            int b2 = buf ^ 1;
#pragma unroll
            for (int i = 0; i < 4; i++)
                As[b2][(kqa * 4 + i) * APAD + ma] = to_tf32(pa[i]);
#pragma unroll
            for (int p = 0; p < 2; p++)
                *(float4*)&Bs[b2][(kqb + p * 8) * BPAD + nb] = pb[p];
        }
        __syncthreads();
    }

#pragma unroll
    for (int mf = 0; mf < 2; mf++) {
        int mrow = m0 + wm + mf * 16 + g;
#pragma unroll
        for (int nf = 0; nf < 4; nf++) {
            int o = n0 + wn + nf * 8 + 2 * t4;
            if (mrow < OSP) {
                part[(size_t)o * OSP + mrow] = acc[mf][nf][0];
                part[(size_t)(o + 1) * OSP + mrow] = acc[mf][nf][1];
            }
            if (mrow + 8 < OSP) {
                part[(size_t)o * OSP + mrow + 8] = acc[mf][nf][2];
                part[(size_t)(o + 1) * OSP + mrow + 8] = acc[mf][nf][3];
            }
        }
    }
}

__global__ void k_c1red(const float* __restrict__ bg, const float* __restrict__ bb,
                        const float* __restrict__ bm, const float* __restrict__ bv) {
    int idx = blockIdx.x * 256 + threadIdx.x;
    if (idx >= IMC_ * OSP) return;
    int o = idx / OSP;
    float s = 0.f;
#pragma unroll
    for (int p = 0; p < 8; p++) s += g_c1part[(size_t)p * IMC_ * OSP + idx];
    float sc = bg[o] / sqrtf(bv[o] + 1e-5f);
    g_y1[idx] = fmaxf((s - bm[o]) * sc + bb[o], 0.f);
}

__global__ void k_c2red(const float* __restrict__ bg, const float* __restrict__ bb,
                        const float* __restrict__ bm, const float* __restrict__ bv,
                        float* __restrict__ out) {
    int idx = blockIdx.x * 256 + threadIdx.x;
    if (idx >= IMC_ * OSP) return;
    int o = idx / OSP;
    float s = 0.f;
#pragma unroll
    for (int p = 0; p < 4; p++) s += g_c2part[(size_t)p * IMC_ * OSP + idx];
    float sc = bg[o] / sqrtf(bv[o] + 1e-5f);
    out[idx] = fmaxf((s - bm[o]) * sc + bb[o], 0.f);
}

// ---------------- launch ----------------
extern "C" void kernel_launch(void* const* d_in, const int* in_sizes, int n_in,
                              void* d_out, int out_size) {
    (void)in_sizes; (void)n_in; (void)out_size;
    const float* f0 = (const float*)d_in[0];
    const float* f1 = (const float*)d_in[1];
    const float* f2 = (const float*)d_in[2];
    const float* f3 = (const float*)d_in[3];
    const float* f4 = (const float*)d_in[4];
    const float* calib = (const float*)d_in[5];
    const float* oftw  = (const float*)d_in[6];
    const float* oftb  = (const float*)d_in[7];
    const float* attw  = (const float*)d_in[8];
    const float* attb  = (const float*)d_in[9];
    const float* c1w   = (const float*)d_in[10];
    const float* b1g   = (const float*)d_in[11];
    const float* b1b   = (const float*)d_in[12];
    const float* b1m   = (const float*)d_in[13];
    const float* b1v   = (const float*)d_in[14];
    const float* c2w   = (const float*)d_in[15];
    const float* b2g   = (const float*)d_in[16];
    const float* b2b   = (const float*)d_in[17];
    const float* b2m   = (const float*)d_in[18];
    const float* b2v   = (const float*)d_in[19];
    float* out = (float*)d_out;

    k_round<<<(2618880 + 255) / 256, 256>>>(f0, f1, f2, f3, f4);
    k_tab<<<(5 * NCELL + 5 * NZ * ND + 255) / 256, 256>>>(calib);
    k_permw<<<(5 * 256 * HC_ + IMC_ * 9 * IMC_ + 255) / 256, 256>>>(oftw, c2w);

    const int pg_smem = STAGES * 2 * 16 * SPAD * 4;   // 52224 B
    cudaFuncSetAttribute(k_pgemm, cudaFuncAttributeMaxDynamicSharedMemorySize, pg_smem);
    k_pgemm<<<dim3(320, 18), 256, pg_smem>>>();

    k_prow<<<(107136 + 255) / 256, 256>>>();
    k_pcol<<<(357120 + 255) / 256, 256>>>();
    k_gather<<<dim3(NCELL / 2, 5), 256>>>(oftb);

    k_colmean<<<CATC, 256>>>();
    k_att<<<5, 256>>>(attw, attb);
    k_wscale<<<(CATC * 9 * IMC_ + 255) / 256, 256>>>(c1w);

    // conv1: K = 1280*9 = 11520, split-K 8 (chunk 1440)
    k_convmma<2, NWC, ND, 1, 1440><<<dim3((OSP + 63) / 64, 2, 8), 256>>>();
    k_c1red<<<(IMC_ * OSP + 255) / 256, 256>>>(b1g, b1b, b1m, b1v);
    // conv2: K = 256*9 = 2304, split-K 4 (chunk 576)
    k_convmma<1, OH1, OW1, 0, 576><<<dim3((OSP + 63) / 64, 2, 4), 256>>>();
    k_c2red<<<(IMC_ * OSP + 255) / 256, 256>>>(b2g, b2b, b2m, b2v, out);
}

// round 16
// speedup vs baseline: 1.1067x; 1.0410x over previous
#include <cuda_runtime.h>
#include <cstdint>

// ---------------- problem constants ----------------
#define NZ 9
#define ND 108          // depth cells (conv W dim)
#define NWC 124         // width cells (conv H dim)
#define NCELL 13392     // ND*NWC
#define IMC_ 256
#define HC_ 2304        // 9*256
#define CATC 1280
#define OH1 62
#define OW1 54
#define OSP 3348        // 62*54

// level geometry
__device__ __constant__ int c_HH[5] = { 96, 48, 24, 12, 6 };
__device__ __constant__ int c_WW[5] = { 320, 160, 80, 40, 20 };
// float-offsets of per-level P buffers (HW*2304)
__device__ __constant__ int c_POFF[5]  = { 0, 70778880, 88473600, 92897280, 94003200 };
// cumulative M-tile (128) counts per level for the fused GEMM
__device__ __constant__ int c_MTCUM[6] = { 0, 240, 300, 315, 319, 320 };
// cumulative thread counts for merged float4 cumsum kernels
__device__ __constant__ int c_RCUM4[6] = { 0, 55296, 82944, 96768, 103680, 107136 };
__device__ __constant__ int c_CCUM4[6] = { 0, 184320, 276480, 322560, 345600, 357120 };

// ---------------- scratch (device globals; no allocs allowed) ----------------
__device__ __align__(16) float g_P[94279680];       // all 5 levels, [z][hw][256] projected maps -> integral
__device__ __align__(16) float g_ctab[5 * NCELL * 12];    // col-tap table per (l,n)
__device__ __align__(16) float g_rtab[5 * NZ * ND * 12];  // row-tap table per (l,z,d)
__device__ __align__(16) float g_wb[5 * 256 * HC_];   // [l][c][z*256+o] tf32-rounded weights
__device__ __align__(16) float g_xcat[CATC * NCELL];  // concat ortho [1280][124][108]
__device__ __align__(16) float g_w1s[CATC * 9 * IMC_];
__device__ __align__(16) float g_w2p[IMC_ * 9 * IMC_];
__device__ float g_colmean[CATC];
__device__ float g_sig[CATC];
__device__ __align__(16) float g_y1[IMC_ * OSP];
__device__ __align__(16) float g_c1part[8 * IMC_ * OSP];
__device__ __align__(16) float g_c2part[4 * IMC_ * OSP];

__device__ __forceinline__ float to_tf32(float x) {
    float r;
    asm("cvt.rna.tf32.f32 %0, %1;" : "=f"(r) : "f"(x));
    return r;
}

__device__ __forceinline__ void cpa16(uint32_t dst, const float* src, bool pred) {
    asm volatile("cp.async.cg.shared.global [%0], [%1], 16, %2;"
                 :: "r"(dst), "l"(src), "r"(pred ? 16 : 0));
}
#define CP_COMMIT() asm volatile("cp.async.commit_group;" ::: "memory")
#define CP_WAIT1()  asm volatile("cp.async.wait_group 1;" ::: "memory")

// ---------------- corner projection (normalized, clamped) ----------------
__device__ __forceinline__ float2 projnc(const float* __restrict__ P, int zi, int di, int wi) {
    float X = 0.64f * (float)di;
    float Y = 39.68f - 0.64f * (float)wi;
    float Z = 2.76f - 0.64f * (float)zi;
    float hx = P[0] * X + P[1] * Y + P[2]  * Z + P[3];
    float hy = P[4] * X + P[5] * Y + P[6]  * Z + P[7];
    float hz = P[8] * X + P[9] * Y + P[10] * Z + P[11];
    float ix = hx / hz, iy = hy / hz;
    float nx = fminf(fmaxf(2.0f * ix / 1280.0f - 1.0f, -1.0f), 1.0f);
    float ny = fminf(fmaxf(2.0f * iy / 384.0f  - 1.0f, -1.0f), 1.0f);
    return make_float2(nx, ny);
}

// ---------------- merged tap tables: ctab (5*NCELL) then rtab (5*NZ*ND) ----------------
__global__ void k_tab(const float* __restrict__ P) {
    int gidx = blockIdx.x * 256 + threadIdx.x;
    if (gidx < 5 * NCELL) {
        int idx = gidx;
        int n = idx % NCELL;
        int l = idx / NCELL;
        int d = n / NWC, w = n - d * NWC;
        int Wf = c_WW[l];

        float xa = projnc(P, 0, d,     w).x;
        float xb = projnc(P, 0, d + 1, w).x;
        float xc = projnc(P, 0, d + 1, w + 1).x;
        float xd = projnc(P, 0, d,     w + 1).x;
        float x1 = fminf(xa, xb);
        float x2 = fmaxf(xc, xd);

        float xp1 = (x1 + 1.f) * (Wf * 0.5f) - 0.5f;
        float xf1 = floorf(xp1); float wx1 = xp1 - xf1; int xi1 = (int)xf1;
        float xp2 = (x2 + 1.f) * (Wf * 0.5f) - 0.5f;
        float xf2 = floorf(xp2); float wx2 = xp2 - xf2; int xi2 = (int)xf2;

        float cw[4]; int co[4]; int ncol;
        if (xi2 == xi1) {
            ncol = 2;
            co[0] = xi1;     cw[0] = wx2 - wx1;
            co[1] = xi1 + 1; cw[1] = wx1 - wx2;
            co[2] = 0; cw[2] = 0.f; co[3] = 0; cw[3] = 0.f;
        } else if (xi2 == xi1 + 1) {
            ncol = 3;
            co[0] = xi1;     cw[0] = 1.f - wx1;
            co[1] = xi1 + 1; cw[1] = wx1 - (1.f - wx2);
            co[2] = xi2 + 1; cw[2] = -wx2;
            co[3] = 0; cw[3] = 0.f;
        } else {
            ncol = 4;
            co[0] = xi1;     cw[0] = 1.f - wx1;
            co[1] = xi1 + 1; cw[1] = wx1;
            co[2] = xi2;     cw[2] = -(1.f - wx2);
            co[3] = xi2 + 1; cw[3] = -wx2;
        }
#pragma unroll
        for (int i = 0; i < 4; i++) {
            bool ok = (co[i] >= 0) && (co[i] < Wf);
            cw[i] = ok ? cw[i] : 0.f;
            co[i] = ok ? co[i] * 256 : 0;
        }
        float* dst = g_ctab + (size_t)idx * 12;
        dst[0] = cw[0]; dst[1] = cw[1]; dst[2] = cw[2]; dst[3] = cw[3];
        ((int*)dst)[4] = co[0]; ((int*)dst)[5] = co[1];
        ((int*)dst)[6] = co[2]; ((int*)dst)[7] = co[3];
        dst[8] = x2 - x1;
        ((int*)dst)[9] = ncol;
        dst[10] = 0.f; dst[11] = 0.f;
    } else {
        int idx = gidx - 5 * NCELL;
        if (idx >= 5 * NZ * ND) return;
        int d = idx % ND;
        int t = idx / ND;
        int z = t % NZ;
        int l = t / NZ;
        int Hf = c_HH[l], Wf = c_WW[l];

        float ya = projnc(P, z,     d,     0).y;
        float yb = projnc(P, z,     d + 1, 0).y;
        float yc = projnc(P, z + 1, d,     0).y;
        float yd = projnc(P, z + 1, d + 1, 0).y;
        float y1 = fminf(ya, yb);
        float y2 = fmaxf(yc, yd);

        float yp1 = (y1 + 1.f) * (Hf * 0.5f) - 0.5f;
        float yf1 = floorf(yp1); float wy1 = yp1 - yf1; int yi1 = (int)yf1;
        float yp2 = (y2 + 1.f) * (Hf * 0.5f) - 0.5f;
        float yf2 = floorf(yp2); float wy2 = yp2 - yf2; int yi2 = (int)yf2;

        float rw[4]; int ro[4]; int nrow;
        if (yi2 == yi1) {
            nrow = 2;
            ro[0] = yi1;     rw[0] = wy2 - wy1;
            ro[1] = yi1 + 1; rw[1] = wy1 - wy2;
            ro[2] = 0; rw[2] = 0.f; ro[3] = 0; rw[3] = 0.f;
        } else if (yi2 == yi1 + 1) {
            nrow = 3;
            ro[0] = yi1;     rw[0] = 1.f - wy1;
            ro[1] = yi1 + 1; rw[1] = wy1 - (1.f - wy2);
            ro[2] = yi2 + 1; rw[2] = -wy2;
            ro[3] = 0; rw[3] = 0.f;
        } else {
            nrow = 4;
            ro[0] = yi1;     rw[0] = 1.f - wy1;
            ro[1] = yi1 + 1; rw[1] = wy1;
            ro[2] = yi2;     rw[2] = -(1.f - wy2);
            ro[3] = yi2 + 1; rw[3] = -wy2;
        }
#pragma unroll
        for (int i = 0; i < 4; i++) {
            bool ok = (ro[i] >= 0) && (ro[i] < Hf);
            rw[i] = ok ? rw[i] : 0.f;
            ro[i] = ok ? ro[i] * Wf * 256 : 0;
        }
        float* dst = g_rtab + (size_t)idx * 12;
        dst[0] = rw[0]; dst[1] = rw[1]; dst[2] = rw[2]; dst[3] = rw[3];
        ((int*)dst)[4] = ro[0]; ((int*)dst)[5] = ro[1];
        ((int*)dst)[6] = ro[2]; ((int*)dst)[7] = ro[3];
        dst[8] = y2 - y1;
        ((int*)dst)[9] = nrow;
        dst[10] = 0.f; dst[11] = 0.f;
    }
}

// ---------------- merged weight permutes: wb (2949120) then w2p (589824) ----------------
__global__ void k_permw(const float* __restrict__ w, const float* __restrict__ w2) {
    int gidx = blockIdx.x * 256 + threadIdx.x;
    if (gidx < 5 * 256 * HC_) {
        int idx = gidx;
        int zo = idx % HC_;
        int t = idx / HC_;
        int c = t & 255;
        int l = t >> 8;
        int z = zo >> 8, o = zo & 255;
        g_wb[idx] = to_tf32(w[((size_t)(l * IMC_ + o)) * HC_ + c * 9 + z]);
    } else {
        int idx = gidx - 5 * 256 * HC_;
        if (idx >= IMC_ * 9 * IMC_) return;
        int o = idx & 255;
        int t = idx >> 8;
        int kk = t % 9;
        int cin = t / 9;
        g_w2p[idx] = to_tf32(w2[(o * IMC_ + cin) * 9 + kk]);
    }
}

// ---------------- tf32 tensor-core GEMM, 3-stage cp.async pipeline ----------------
// A loaded raw fp32 from input feats: tf32 MMA reads top 19 bits (truncation in
// place of explicit RNA rounding). B remains RNA-rounded in k_permw.
#define SPAD 136
#define STAGES 3
#define STAGEF (16 * SPAD)
__global__ __launch_bounds__(256) void k_pgemm(
    const float* __restrict__ f0, const float* __restrict__ f1,
    const float* __restrict__ f2, const float* __restrict__ f3,
    const float* __restrict__ f4) {
    extern __shared__ float sm[];
    float* As = sm;                      // [STAGES][16*SPAD]
    float* Bs = sm + STAGES * STAGEF;    // [STAGES][16*SPAD]

    int bx = blockIdx.x;
    int l = 0;
    while (bx >= c_MTCUM[l + 1]) l++;
    int mtile = bx - c_MTCUM[l];
    int HW = c_HH[l] * c_WW[l];
    const float* __restrict__ Ag = (l == 0) ? f0 : (l == 1) ? f1 : (l == 2) ? f2 : (l == 3) ? f3 : f4;
    const float* __restrict__ Bg = g_wb + (size_t)l * 256 * HC_;
    float* __restrict__ P = g_P + c_POFF[l];

    int tid = threadIdx.x;
    int m0 = mtile * 128;
    int n0 = blockIdx.y * 128;

    int lane = tid & 31;
    int g = lane >> 2, t = lane & 3;
    int wid = tid >> 5;
    int wm = (wid & 1) * 64;
    int wn = (wid >> 1) * 32;

    float acc[4][4][4];
#pragma unroll
    for (int i = 0; i < 4; i++)
#pragma unroll
        for (int j = 0; j < 4; j++)
#pragma unroll
            for (int q = 0; q < 4; q++) acc[i][j][q] = 0.f;

    int ka0 = tid >> 5, ma0 = (tid & 31) * 4;
    int ka1 = (tid + 256) >> 5;
    int gm = m0 + ma0;
    bool gmv = gm < HW;

    uint32_t asb = (uint32_t)__cvta_generic_to_shared(As);
    uint32_t bsb = (uint32_t)__cvta_generic_to_shared(Bs);
    uint32_t adst0 = asb + (uint32_t)(ka0 * SPAD + ma0) * 4;
    uint32_t adst1 = asb + (uint32_t)(ka1 * SPAD + ma0) * 4;
    uint32_t bdst0 = bsb + (uint32_t)(ka0 * SPAD + ma0) * 4;
    uint32_t bdst1 = bsb + (uint32_t)(ka1 * SPAD + ma0) * 4;
    const uint32_t sbytes = STAGEF * 4;

    const int NKT = 16;
#pragma unroll
    for (int s = 0; s < 2; s++) {
        int c0 = s * 16;
        cpa16(adst0 + s * sbytes, Ag + (size_t)(c0 + ka0) * HW + gm, gmv);
        cpa16(adst1 + s * sbytes, Ag + (size_t)(c0 + ka1) * HW + gm, gmv);
        cpa16(bdst0 + s * sbytes, Bg + (size_t)(c0 + ka0) * HC_ + n0 + ma0, true);
        cpa16(bdst1 + s * sbytes, Bg + (size_t)(c0 + ka1) * HC_ + n0 + ma0, true);
        CP_COMMIT();
    }

    int buf = 0;
    for (int kt = 0; kt < NKT; kt++) {
        CP_WAIT1();
        __syncthreads();
        if (kt + 2 < NKT) {
            int s = buf + 2; if (s >= 3) s -= 3;
            int c0 = (kt + 2) * 16;
            cpa16(adst0 + s * sbytes, Ag + (size_t)(c0 + ka0) * HW + gm, gmv);
            cpa16(adst1 + s * sbytes, Ag + (size_t)(c0 + ka1) * HW + gm, gmv);
            cpa16(bdst0 + s * sbytes, Bg + (size_t)(c0 + ka0) * HC_ + n0 + ma0, true);
            cpa16(bdst1 + s * sbytes, Bg + (size_t)(c0 + ka1) * HC_ + n0 + ma0, true);
        }
        CP_COMMIT();

        const float* Ab = As + buf * STAGEF;
        const float* Bb = Bs + buf * STAGEF;
#pragma unroll
        for (int ks = 0; ks < 2; ks++) {
            int kk = ks * 8;
            uint32_t af[4][4], bf[4][2];
#pragma unroll
            for (int mf = 0; mf < 4; mf++) {
                int m = wm + mf * 16 + g;
                af[mf][0] = __float_as_uint(Ab[(kk + t) * SPAD + m]);
                af[mf][1] = __float_as_uint(Ab[(kk + t) * SPAD + m + 8]);
                af[mf][2] = __float_as_uint(Ab[(kk + t + 4) * SPAD + m]);
                af[mf][3] = __float_as_uint(Ab[(kk + t + 4) * SPAD + m + 8]);
            }
#pragma unroll
            for (int nf = 0; nf < 4; nf++) {
                int n = wn + nf * 8 + g;
                bf[nf][0] = __float_as_uint(Bb[(kk + t) * SPAD + n]);
                bf[nf][1] = __float_as_uint(Bb[(kk + t + 4) * SPAD + n]);
            }
#pragma unroll
            for (int mf = 0; mf < 4; mf++)
#pragma unroll
                for (int nf = 0; nf < 4; nf++) {
                    asm volatile(
                        "mma.sync.aligned.m16n8k8.row.col.f32.tf32.tf32.f32 "
                        "{%0,%1,%2,%3}, {%4,%5,%6,%7}, {%8,%9}, {%0,%1,%2,%3};"
                        : "+f"(acc[mf][nf][0]), "+f"(acc[mf][nf][1]),
                          "+f"(acc[mf][nf][2]), "+f"(acc[mf][nf][3])
                        : "r"(af[mf][0]), "r"(af[mf][1]), "r"(af[mf][2]), "r"(af[mf][3]),
                          "r"(bf[nf][0]), "r"(bf[nf][1]));
                }
        }
        buf = (buf == 2) ? 0 : buf + 1;
    }

    int z = n0 >> 8;
    int ob0 = n0 & 255;
#pragma unroll
    for (int mf = 0; mf < 4; mf++) {
        int m = m0 + wm + mf * 16 + g;
#pragma unroll
        for (int nf = 0; nf < 4; nf++) {
            int o = ob0 + wn + nf * 8 + 2 * t;
            if (m < HW) {
                float* dst = P + ((size_t)z * HW + m) * 256 + o;
                *(float2*)dst = make_float2(acc[mf][nf][0], acc[mf][nf][1]);
            }
            if (m + 8 < HW) {
                float* dst = P + ((size_t)z * HW + m + 8) * 256 + o;
                *(float2*)dst = make_float2(acc[mf][nf][2], acc[mf][nf][3]);
            }
        }
    }
}

// ---------------- merged float4 cumsum of P along w (all levels) ----------------
__global__ void k_prow(void) {
    int t = blockIdx.x * 256 + threadIdx.x;
    if (t >= 107136) return;
    int l = 0;
    while (t >= c_RCUM4[l + 1]) l++;
    int tt = t - c_RCUM4[l];
    int H = c_HH[l], W = c_WW[l];
    int o4 = (tt & 63) * 4;
    int r = tt >> 6;
    int h = r % H, z = r / H;
    float* p = g_P + c_POFF[l] + ((size_t)(z * H + h) * W) * 256 + o4;
    float4 a = make_float4(0, 0, 0, 0);
    for (int w = 0; w < W; w += 4) {
        float4 v0 = *(float4*)(p + (w + 0) * 256);
        float4 v1 = *(float4*)(p + (w + 1) * 256);
        float4 v2 = *(float4*)(p + (w + 2) * 256);
        float4 v3 = *(float4*)(p + (w + 3) * 256);
        a.x += v0.x; a.y += v0.y; a.z += v0.z; a.w += v0.w;
        *(float4*)(p + (w + 0) * 256) = a;
        a.x += v1.x; a.y += v1.y; a.z += v1.z; a.w += v1.w;
        *(float4*)(p + (w + 1) * 256) = a;
        a.x += v2.x; a.y += v2.y; a.z += v2.z; a.w += v2.w;
        *(float4*)(p + (w + 2) * 256) = a;
        a.x += v3.x; a.y += v3.y; a.z += v3.z; a.w += v3.w;
        *(float4*)(p + (w + 3) * 256) = a;
    }
}

// ---------------- merged float4 cumsum of P along h (all levels), unroll 6 ----------------
__global__ void k_pcol(void) {
    int t = blockIdx.x * 256 + threadIdx.x;
    if (t >= 357120) return;
    int l = 0;
    while (t >= c_CCUM4[l + 1]) l++;
    int tt = t - c_CCUM4[l];
    int H = c_HH[l], W = c_WW[l];
    int o4 = (tt & 63) * 4;
    int r = tt >> 6;
    int w = r % W, z = r / W;
    float* p = g_P + c_POFF[l] + ((size_t)z * H * W + w) * 256 + o4;
    int stride = W * 256;
    float4 a = make_float4(0, 0, 0, 0);
    for (int h = 0; h < H; h += 6) {
        float4 v0 = *(float4*)(p + (h + 0) * stride);
        float4 v1 = *(float4*)(p + (h + 1) * stride);
        float4 v2 = *(float4*)(p + (h + 2) * stride);
        float4 v3 = *(float4*)(p + (h + 3) * stride);
        float4 v4 = *(float4*)(p + (h + 4) * stride);
        float4 v5 = *(float4*)(p + (h + 5) * stride);
        a.x += v0.x; a.y += v0.y; a.z += v0.z; a.w += v0.w;
        *(float4*)(p + (h + 0) * stride) = a;
        a.x += v1.x; a.y += v1.y; a.z += v1.z; a.w += v1.w;
        *(float4*)(p + (h + 1) * stride) = a;
        a.x += v2.x; a.y += v2.y; a.z += v2.z; a.w += v2.w;
        *(float4*)(p + (h + 2) * stride) = a;
        a.x += v3.x; a.y += v3.y; a.z += v3.z; a.w += v3.w;
        *(float4*)(p + (h + 3) * stride) = a;
        a.x += v4.x; a.y += v4.y; a.z += v4.z; a.w += v4.w;
        *(float4*)(p + (h + 4) * stride) = a;
        a.x += v5.x; a.y += v5.y; a.z += v5.z; a.w += v5.w;
        *(float4*)(p + (h + 5) * stride) = a;
    }
}

// ---------------- fused gather (dedup-table-driven, R7/R13 structure) ----------------
__global__ __launch_bounds__(256) void k_gather(const float* __restrict__ bias) {
    int n = blockIdx.x;
    int l = blockIdx.y;
    int o = threadIdx.x;
    int Hf = c_HH[l], Wf = c_WW[l];
    int HW = Hf * Wf;
    float areaF = (float)HW * 0.25f;
    const float* __restrict__ P = g_P + c_POFF[l];
    int d = n / NWC;

    const float* ct = g_ctab + (size_t)(l * NCELL + n) * 12;
    float4 cw = *(const float4*)ct;
    int4 co = *(const int4*)(ct + 4);
    float xw = ct[8];
    int ncol = ((const int*)ct)[9];

    float acc = bias[l * 256 + o];

    const float* tab = g_rtab + (size_t)((l * NZ) * ND + d) * 12;
#pragma unroll
    for (int z = 0; z < NZ; z++, tab += ND * 12) {
        float4 rw = *(const float4*)tab;
        int4 ro = *(const int4*)(tab + 4);
        float yh = tab[8];
        int nrow = ((const int*)tab)[9];
        float area = xw * yh * areaF + 1e-6f;
        if (!(area > 1e-6f)) continue;
        float inv = 1.0f / area;
        const float* Pz = P + (size_t)z * HW * 256 + o;

        const float* Pr0 = Pz + ro.x;
        float rs0 = cw.x * Pr0[co.x] + cw.y * Pr0[co.y];
        if (ncol > 2) rs0 += cw.z * Pr0[co.z];
        if (ncol > 3) rs0 += cw.w * Pr0[co.w];
        const float* Pr1 = Pz + ro.y;
        float rs1 = cw.x * Pr1[co.x] + cw.y * Pr1[co.y];
        if (ncol > 2) rs1 += cw.z * Pr1[co.z];
        if (ncol > 3) rs1 += cw.w * Pr1[co.w];
        float s = rw.x * rs0 + rw.y * rs1;
        if (nrow > 2) {
            const float* Pr2 = Pz + ro.z;
            float rs2 = cw.x * Pr2[co.x] + cw.y * Pr2[co.y];
            if (ncol > 2) rs2 += cw.z * Pr2[co.z];
            if (ncol > 3) rs2 += cw.w * Pr2[co.w];
            s += rw.z * rs2;
        }
        if (nrow > 3) {
            const float* Pr3 = Pz + ro.w;
            float rs3 = cw.x * Pr3[co.x] + cw.y * Pr3[co.y];
            if (ncol > 2) rs3 += cw.z * Pr3[co.z];
            if (ncol > 3) rs3 += cw.w * Pr3[co.w];
            s += rw.w * rs3;
        }
        acc += inv * s;
    }
    int w = n - d * NWC;
    int sp = w * ND + d;
    g_xcat[(l * 256 + o) * NCELL + sp] = fmaxf(acc, 0.0f);
}

// ---------------- channel means (float4) ----------------
__global__ void k_colmean() {
    int g = blockIdx.x;
    const float4* p = (const float4*)(g_xcat + (size_t)g * NCELL);
    float s = 0.f;
    for (int i = threadIdx.x; i < NCELL / 4; i += 256) {
        float4 v = p[i];
        s += v.x + v.y + v.z + v.w;
    }
    __shared__ float sm[256];
    sm[threadIdx.x] = s;
    __syncthreads();
    for (int st = 128; st > 0; st >>= 1) {
        if (threadIdx.x < st) sm[threadIdx.x] += sm[threadIdx.x + st];
        __syncthreads();
    }
    if (threadIdx.x == 0) g_colmean[g] = sm[0] * (1.0f / (float)NCELL);
}

__global__ void k_att(const float* __restrict__ aw, const float* __restrict__ ab) {
    __shared__ float cm[IMC_];
    int l = blockIdx.x, o = threadIdx.x;
    cm[o] = g_colmean[l * IMC_ + o];
    __syncthreads();
    float acc = ab[o];
    for (int c = 0; c < IMC_; c++) acc += cm[c] * aw[o * IMC_ + c];
    g_sig[l * IMC_ + o] = 1.0f / (1.0f + expf(-acc));
}

// ---------------- fold attention + transpose conv1 weights -> tf32 [k][o] ----------------
__global__ void k_wscale(const float* __restrict__ w) {
    int idx = blockIdx.x * 256 + threadIdx.x;
    if (idx >= CATC * 9 * IMC_) return;
    int o = idx & 255;
    int t = idx >> 8;
    int kk = t % 9;
    int cin = t / 9;
    g_w1s[idx] = to_tf32(w[(o * CATC + cin) * 9 + kk] * g_sig[cin]);
}

// ---------------- implicit-GEMM tf32 conv (3x3, pad 1), split-K partials ----------------
#define APAD 68
#define BPAD 132
template<int STRIDE, int IH, int IW, int CONV1, int KCHUNK>
__global__ __launch_bounds__(256) void k_convmma() {
    const float* __restrict__ src = CONV1 ? g_xcat : g_y1;
    const float* __restrict__ wt  = CONV1 ? g_w1s : g_w2p;
    float* __restrict__ part = (CONV1 ? g_c1part : g_c2part) + (size_t)blockIdx.z * IMC_ * OSP;

    __shared__ float As[2][16 * APAD];
    __shared__ float Bs[2][16 * BPAD];

    int tid = threadIdx.x;
    int m0 = blockIdx.x * 64;
    int n0 = blockIdx.y * 128;
    int kbase = blockIdx.z * KCHUNK;

    int lane = tid & 31;
    int g = lane >> 2, t4 = lane & 3;
    int wid = tid >> 5;
    int wm = (wid & 1) * 32;
    int wn = (wid >> 1) * 32;

    int ma = tid & 63;
    int kqa = tid >> 6;
    int m = m0 + ma;
    bool mv = m < OSP;
    int mq = mv ? m : 0;
    int oh = mq / OW1, ow = mq - oh * OW1;
    int ihb = STRIDE * oh - 1, iwb = STRIDE * ow - 1;

    int nb = (tid & 31) * 4;
    int kqb = tid >> 5;

    float acc[2][4][4];
#pragma unroll
    for (int i = 0; i < 2; i++)
#pragma unroll
        for (int j = 0; j < 4; j++)
#pragma unroll
            for (int q = 0; q < 4; q++) acc[i][j][q] = 0.f;

    {
#pragma unroll
        for (int i = 0; i < 4; i++) {
            int kg = kbase + kqa * 4 + i;
            int cin = kg / 9; int r = kg - cin * 9;
            int ky = r / 3, kx = r - ky * 3;
            int ih = ihb + ky, iw = iwb + kx;
            bool ok = mv && ih >= 0 && ih < IH && iw >= 0 && iw < IW;
            float v = ok ? src[(size_t)cin * (IH * IW) + ih * IW + iw] : 0.f;
            As[0][(kqa * 4 + i) * APAD + ma] = to_tf32(v);
        }
#pragma unroll
        for (int p = 0; p < 2; p++) {
            int kk = kqb + p * 8;
            *(float4*)&Bs[0][kk * BPAD + nb] = *(const float4*)(wt + (size_t)(kbase + kk) * 256 + n0 + nb);
        }
    }
    __syncthreads();

    const int NT = KCHUNK / 16;
    for (int kt = 0; kt < NT; kt++) {
        int buf = kt & 1;
        float pa[4];
        float4 pb[2];
        if (kt + 1 < NT) {
            int k0n = kbase + (kt + 1) * 16;
#pragma unroll
            for (int i = 0; i < 4; i++) {
                int kg = k0n + kqa * 4 + i;
                int cin = kg / 9; int r = kg - cin * 9;
                int ky = r / 3, kx = r - ky * 3;
                int ih = ihb + ky, iw = iwb + kx;
                bool ok = mv && ih >= 0 && ih < IH && iw >= 0 && iw < IW;
                pa[i] = ok ? src[(size_t)cin * (IH * IW) + ih * IW + iw] : 0.f;
            }
#pragma unroll
            for (int p = 0; p < 2; p++) {
                int kk = kqb + p * 8;
                pb[p] = *(const float4*)(wt + (size_t)(k0n + kk) * 256 + n0 + nb);
            }
        }
#pragma unroll
        for (int ks = 0; ks < 2; ks++) {
            int kk = ks * 8;
            uint32_t af[2][4], bf[4][2];
#pragma unroll
            for (int mf = 0; mf < 2; mf++) {
                int mm = wm + mf * 16 + g;
                af[mf][0] = __float_as_uint(As[buf][(kk + t4) * APAD + mm]);
                af[mf][1] = __float_as_uint(As[buf][(kk + t4) * APAD + mm + 8]);
                af[mf][2] = __float_as_uint(As[buf][(kk + t4 + 4) * APAD + mm]);
                af[mf][3] = __float_as_uint(As[buf][(kk + t4 + 4) * APAD + mm + 8]);
            }
#pragma unroll
            for (int nf = 0; nf < 4; nf++) {
                int nn = wn + nf * 8 + g;
                bf[nf][0] = __float_as_uint(Bs[buf][(kk + t4) * BPAD + nn]);
                bf[nf][1] = __float_as_uint(Bs[buf][(kk + t4 + 4) * BPAD + nn]);
            }
#pragma unroll
            for (int mf = 0; mf < 2; mf++)
#pragma unroll
                for (int nf = 0; nf < 4; nf++) {
                    asm volatile(
                        "mma.sync.aligned.m16n8k8.row.col.f32.tf32.tf32.f32 "
                        "{%0,%1,%2,%3}, {%4,%5,%6,%7}, {%8,%9}, {%0,%1,%2,%3};"
                        : "+f"(acc[mf][nf][0]), "+f"(acc[mf][nf][1]),
                          "+f"(acc[mf][nf][2]), "+f"(acc[mf][nf][3])
                        : "r"(af[mf][0]), "r"(af[mf][1]), "r"(af[mf][2]), "r"(af[mf][3]),
                          "r"(bf[nf][0]), "r"(bf[nf][1]));
                }
        }
        if (kt + 1 < NT) {
            int b2 = buf ^ 1;
#pragma unroll
            for (int i = 0; i < 4; i++)
                As[b2][(kqa * 4 + i) * APAD + ma] = to_tf32(pa[i]);
#pragma unroll
            for (int p = 0; p < 2; p++)
                *(float4*)&Bs[b2][(kqb + p * 8) * BPAD + nb] = pb[p];
        }
        __syncthreads();
    }

#pragma unroll
    for (int mf = 0; mf < 2; mf++) {
        int mrow = m0 + wm + mf * 16 + g;
#pragma unroll
        for (int nf = 0; nf < 4; nf++) {
            int o = n0 + wn + nf * 8 + 2 * t4;
            if (mrow < OSP) {
                part[(size_t)o * OSP + mrow] = acc[mf][nf][0];
                part[(size_t)(o + 1) * OSP + mrow] = acc[mf][nf][1];
            }
            if (mrow + 8 < OSP) {
                part[(size_t)o * OSP + mrow + 8] = acc[mf][nf][2];
                part[(size_t)(o + 1) * OSP + mrow + 8] = acc[mf][nf][3];
            }
        }
    }
}

__global__ void k_c1red(const float* __restrict__ bg, const float* __restrict__ bb,
                        const float* __restrict__ bm, const float* __restrict__ bv) {
    int idx = blockIdx.x * 256 + threadIdx.x;
    if (idx >= IMC_ * OSP) return;
    int o = idx / OSP;
    float s = 0.f;
#pragma unroll
    for (int p = 0; p < 8; p++) s += g_c1part[(size_t)p * IMC_ * OSP + idx];
    float sc = bg[o] / sqrtf(bv[o] + 1e-5f);
    g_y1[idx] = fmaxf((s - bm[o]) * sc + bb[o], 0.f);
}

__global__ void k_c2red(const float* __restrict__ bg, const float* __restrict__ bb,
                        const float* __restrict__ bm, const float* __restrict__ bv,
                        float* __restrict__ out) {
    int idx = blockIdx.x * 256 + threadIdx.x;
    if (idx >= IMC_ * OSP) return;
    int o = idx / OSP;
    float s = 0.f;
#pragma unroll
    for (int p = 0; p < 4; p++) s += g_c2part[(size_t)p * IMC_ * OSP + idx];
    float sc = bg[o] / sqrtf(bv[o] + 1e-5f);
    out[idx] = fmaxf((s - bm[o]) * sc + bb[o], 0.f);
}

// ---------------- launch ----------------
extern "C" void kernel_launch(void* const* d_in, const int* in_sizes, int n_in,
                              void* d_out, int out_size) {
    (void)in_sizes; (void)n_in; (void)out_size;
    const float* f0 = (const float*)d_in[0];
    const float* f1 = (const float*)d_in[1];
    const float* f2 = (const float*)d_in[2];
    const float* f3 = (const float*)d_in[3];
    const float* f4 = (const float*)d_in[4];
    const float* calib = (const float*)d_in[5];
    const float* oftw  = (const float*)d_in[6];
    const float* oftb  = (const float*)d_in[7];
    const float* attw  = (const float*)d_in[8];
    const float* attb  = (const float*)d_in[9];
    const float* c1w   = (const float*)d_in[10];
    const float* b1g   = (const float*)d_in[11];
    const float* b1b   = (const float*)d_in[12];
    const float* b1m   = (const float*)d_in[13];
    const float* b1v   = (const float*)d_in[14];
    const float* c2w   = (const float*)d_in[15];
    const float* b2g   = (const float*)d_in[16];
    const float* b2b   = (const float*)d_in[17];
    const float* b2m   = (const float*)d_in[18];
    const float* b2v   = (const float*)d_in[19];
    float* out = (float*)d_out;

    k_tab<<<(5 * NCELL + 5 * NZ * ND + 255) / 256, 256>>>(calib);
    k_permw<<<(5 * 256 * HC_ + IMC_ * 9 * IMC_ + 255) / 256, 256>>>(oftw, c2w);

    const int pg_smem = STAGES * 2 * 16 * SPAD * 4;   // 52224 B
    cudaFuncSetAttribute(k_pgemm, cudaFuncAttributeMaxDynamicSharedMemorySize, pg_smem);
    k_pgemm<<<dim3(320, 18), 256, pg_smem>>>(f0, f1, f2, f3, f4);

    k_prow<<<(107136 + 255) / 256, 256>>>();
    k_pcol<<<(357120 + 255) / 256, 256>>>();
    k_gather<<<dim3(NCELL, 5), 256>>>(oftb);

    k_colmean<<<CATC, 256>>>();
    k_att<<<5, 256>>>(attw, attb);
    k_wscale<<<(CATC * 9 * IMC_ + 255) / 256, 256>>>(c1w);

    // conv1: K = 1280*9 = 11520, split-K 8 (chunk 1440)
    k_convmma<2, NWC, ND, 1, 1440><<<dim3((OSP + 63) / 64, 2, 8), 256>>>();
    k_c1red<<<(IMC_ * OSP + 255) / 256, 256>>>(b1g, b1b, b1m, b1v);
    // conv2: K = 256*9 = 2304, split-K 4 (chunk 576)
    k_convmma<1, OH1, OW1, 0, 576><<<dim3((OSP + 63) / 64, 2, 4), 256>>>();
    k_c2red<<<(IMC_ * OSP + 255) / 256, 256>>>(b2g, b2b, b2m, b2v, out);
}

// round 17
// speedup vs baseline: 1.1157x; 1.0082x over previous
#include <cuda_runtime.h>
#include <cstdint>

// ---------------- problem constants ----------------
#define NZ 9
#define ND 108          // depth cells (conv W dim)
#define NWC 124         // width cells (conv H dim)
#define NCELL 13392     // ND*NWC
#define IMC_ 256
#define HC_ 2304        // 9*256
#define CATC 1280
#define OH1 62
#define OW1 54
#define OSP 3348        // 62*54

// level geometry
__device__ __constant__ int c_HH[5] = { 96, 48, 24, 12, 6 };
__device__ __constant__ int c_WW[5] = { 320, 160, 80, 40, 20 };
// float-offsets of per-level P buffers (HW*2304)
__device__ __constant__ int c_POFF[5]  = { 0, 70778880, 88473600, 92897280, 94003200 };
// cumulative M-tile (128) counts per level for the fused GEMM
__device__ __constant__ int c_MTCUM[6] = { 0, 240, 300, 315, 319, 320 };
// cumulative thread counts for merged float4 cumsum kernels
__device__ __constant__ int c_RCUM4[6] = { 0, 55296, 82944, 96768, 103680, 107136 };
__device__ __constant__ int c_CCUM4[6] = { 0, 184320, 276480, 322560, 345600, 357120 };

// ---------------- scratch (device globals; no allocs allowed) ----------------
__device__ __align__(16) float g_P[94279680];       // all 5 levels, [z][hw][256] projected maps -> integral
__device__ __align__(16) float g_ctab[5 * NCELL * 12];    // col-tap table per (l,n)
__device__ __align__(16) float g_rtab[5 * NZ * ND * 12];  // row-tap table per (l,z,d)
__device__ __align__(16) float g_wb[5 * 256 * HC_];   // [l][c][z*256+o] tf32-rounded weights
__device__ __align__(16) float g_xcat[CATC * NCELL];  // concat ortho [1280][124][108]
__device__ __align__(16) float g_w1s[CATC * 9 * IMC_];
__device__ __align__(16) float g_w2p[IMC_ * 9 * IMC_];
__device__ float g_colmean[CATC];
__device__ float g_sig[CATC];
__device__ __align__(16) float g_y1[IMC_ * OSP];
__device__ __align__(16) float g_c1part[8 * IMC_ * OSP];
__device__ __align__(16) float g_c2part[4 * IMC_ * OSP];

__device__ __forceinline__ float to_tf32(float x) {
    float r;
    asm("cvt.rna.tf32.f32 %0, %1;" : "=f"(r) : "f"(x));
    return r;
}

__device__ __forceinline__ void cpa16(uint32_t dst, const float* src, bool pred) {
    asm volatile("cp.async.cg.shared.global [%0], [%1], 16, %2;"
                 :: "r"(dst), "l"(src), "r"(pred ? 16 : 0));
}
#define CP_COMMIT() asm volatile("cp.async.commit_group;" ::: "memory")
#define CP_WAIT1()  asm volatile("cp.async.wait_group 1;" ::: "memory")

// ---------------- corner projection (normalized, clamped) ----------------
__device__ __forceinline__ float2 projnc(const float* __restrict__ P, int zi, int di, int wi) {
    float X = 0.64f * (float)di;
    float Y = 39.68f - 0.64f * (float)wi;
    float Z = 2.76f - 0.64f * (float)zi;
    float hx = P[0] * X + P[1] * Y + P[2]  * Z + P[3];
    float hy = P[4] * X + P[5] * Y + P[6]  * Z + P[7];
    float hz = P[8] * X + P[9] * Y + P[10] * Z + P[11];
    float ix = hx / hz, iy = hy / hz;
    float nx = fminf(fmaxf(2.0f * ix / 1280.0f - 1.0f, -1.0f), 1.0f);
    float ny = fminf(fmaxf(2.0f * iy / 384.0f  - 1.0f, -1.0f), 1.0f);
    return make_float2(nx, ny);
}

// ---------------- merged tap tables: ctab (5*NCELL) then rtab (5*NZ*ND) ----------------
__global__ void k_tab(const float* __restrict__ P) {
    int gidx = blockIdx.x * 256 + threadIdx.x;
    if (gidx < 5 * NCELL) {
        int idx = gidx;
        int n = idx % NCELL;
        int l = idx / NCELL;
        int d = n / NWC, w = n - d * NWC;
        int Wf = c_WW[l];

        float xa = projnc(P, 0, d,     w).x;
        float xb = projnc(P, 0, d + 1, w).x;
        float xc = projnc(P, 0, d + 1, w + 1).x;
        float xd = projnc(P, 0, d,     w + 1).x;
        float x1 = fminf(xa, xb);
        float x2 = fmaxf(xc, xd);

        float xp1 = (x1 + 1.f) * (Wf * 0.5f) - 0.5f;
        float xf1 = floorf(xp1); float wx1 = xp1 - xf1; int xi1 = (int)xf1;
        float xp2 = (x2 + 1.f) * (Wf * 0.5f) - 0.5f;
        float xf2 = floorf(xp2); float wx2 = xp2 - xf2; int xi2 = (int)xf2;

        float cw[4]; int co[4]; int ncol;
        if (xi2 == xi1) {
            ncol = 2;
            co[0] = xi1;     cw[0] = wx2 - wx1;
            co[1] = xi1 + 1; cw[1] = wx1 - wx2;
            co[2] = 0; cw[2] = 0.f; co[3] = 0; cw[3] = 0.f;
        } else if (xi2 == xi1 + 1) {
            ncol = 3;
            co[0] = xi1;     cw[0] = 1.f - wx1;
            co[1] = xi1 + 1; cw[1] = wx1 - (1.f - wx2);
            co[2] = xi2 + 1; cw[2] = -wx2;
            co[3] = 0; cw[3] = 0.f;
        } else {
            ncol = 4;
            co[0] = xi1;     cw[0] = 1.f - wx1;
            co[1] = xi1 + 1; cw[1] = wx1;
            co[2] = xi2;     cw[2] = -(1.f - wx2);
            co[3] = xi2 + 1; cw[3] = -wx2;
        }
#pragma unroll
        for (int i = 0; i < 4; i++) {
            bool ok = (co[i] >= 0) && (co[i] < Wf);
            cw[i] = ok ? cw[i] : 0.f;
            co[i] = ok ? co[i] * 256 : 0;
        }
        float* dst = g_ctab + (size_t)idx * 12;
        dst[0] = cw[0]; dst[1] = cw[1]; dst[2] = cw[2]; dst[3] = cw[3];
        ((int*)dst)[4] = co[0]; ((int*)dst)[5] = co[1];
        ((int*)dst)[6] = co[2]; ((int*)dst)[7] = co[3];
        dst[8] = x2 - x1;
        ((int*)dst)[9] = ncol;
        dst[10] = 0.f; dst[11] = 0.f;
    } else {
        int idx = gidx - 5 * NCELL;
        if (idx >= 5 * NZ * ND) return;
        int d = idx % ND;
        int t = idx / ND;
        int z = t % NZ;
        int l = t / NZ;
        int Hf = c_HH[l], Wf = c_WW[l];

        float ya = projnc(P, z,     d,     0).y;
        float yb = projnc(P, z,     d + 1, 0).y;
        float yc = projnc(P, z + 1, d,     0).y;
        float yd = projnc(P, z + 1, d + 1, 0).y;
        float y1 = fminf(ya, yb);
        float y2 = fmaxf(yc, yd);

        float yp1 = (y1 + 1.f) * (Hf * 0.5f) - 0.5f;
        float yf1 = floorf(yp1); float wy1 = yp1 - yf1; int yi1 = (int)yf1;
        float yp2 = (y2 + 1.f) * (Hf * 0.5f) - 0.5f;
        float yf2 = floorf(yp2); float wy2 = yp2 - yf2; int yi2 = (int)yf2;

        float rw[4]; int ro[4]; int nrow;
        if (yi2 == yi1) {
            nrow = 2;
            ro[0] = yi1;     rw[0] = wy2 - wy1;
            ro[1] = yi1 + 1; rw[1] = wy1 - wy2;
            ro[2] = 0; rw[2] = 0.f; ro[3] = 0; rw[3] = 0.f;
        } else if (yi2 == yi1 + 1) {
            nrow = 3;
            ro[0] = yi1;     rw[0] = 1.f - wy1;
            ro[1] = yi1 + 1; rw[1] = wy1 - (1.f - wy2);
            ro[2] = yi2 + 1; rw[2] = -wy2;
            ro[3] = 0; rw[3] = 0.f;
        } else {
            nrow = 4;
            ro[0] = yi1;     rw[0] = 1.f - wy1;
            ro[1] = yi1 + 1; rw[1] = wy1;
            ro[2] = yi2;     rw[2] = -(1.f - wy2);
            ro[3] = yi2 + 1; rw[3] = -wy2;
        }
#pragma unroll
        for (int i = 0; i < 4; i++) {
            bool ok = (ro[i] >= 0) && (ro[i] < Hf);
            rw[i] = ok ? rw[i] : 0.f;
            ro[i] = ok ? ro[i] * Wf * 256 : 0;
        }
        float* dst = g_rtab + (size_t)idx * 12;
        dst[0] = rw[0]; dst[1] = rw[1]; dst[2] = rw[2]; dst[3] = rw[3];
        ((int*)dst)[4] = ro[0]; ((int*)dst)[5] = ro[1];
        ((int*)dst)[6] = ro[2]; ((int*)dst)[7] = ro[3];
        dst[8] = y2 - y1;
        ((int*)dst)[9] = nrow;
        dst[10] = 0.f; dst[11] = 0.f;
    }
}

// ---------------- merged weight permutes: wb (2949120) then w2p (589824) ----------------
__global__ void k_permw(const float* __restrict__ w, const float* __restrict__ w2) {
    int gidx = blockIdx.x * 256 + threadIdx.x;
    if (gidx < 5 * 256 * HC_) {
        int idx = gidx;
        int zo = idx % HC_;
        int t = idx / HC_;
        int c = t & 255;
        int l = t >> 8;
        int z = zo >> 8, o = zo & 255;
        g_wb[idx] = to_tf32(w[((size_t)(l * IMC_ + o)) * HC_ + c * 9 + z]);
    } else {
        int idx = gidx - 5 * 256 * HC_;
        if (idx >= IMC_ * 9 * IMC_) return;
        int o = idx & 255;
        int t = idx >> 8;
        int kk = t % 9;
        int cin = t / 9;
        g_w2p[idx] = to_tf32(w2[(o * IMC_ + cin) * 9 + kk]);
    }
}

// ---------------- tf32 tensor-core GEMM, 3-stage cp.async pipeline ----------------
#define SPAD 136
#define STAGES 3
#define STAGEF (16 * SPAD)
__global__ __launch_bounds__(256) void k_pgemm(
    const float* __restrict__ f0, const float* __restrict__ f1,
    const float* __restrict__ f2, const float* __restrict__ f3,
    const float* __restrict__ f4) {
    extern __shared__ float sm[];
    float* As = sm;
    float* Bs = sm + STAGES * STAGEF;

    int bx = blockIdx.x;
    int l = 0;
    while (bx >= c_MTCUM[l + 1]) l++;
    int mtile = bx - c_MTCUM[l];
    int HW = c_HH[l] * c_WW[l];
    const float* __restrict__ Ag = (l == 0) ? f0 : (l == 1) ? f1 : (l == 2) ? f2 : (l == 3) ? f3 : f4;
    const float* __restrict__ Bg = g_wb + (size_t)l * 256 * HC_;
    float* __restrict__ P = g_P + c_POFF[l];

    int tid = threadIdx.x;
    int m0 = mtile * 128;
    int n0 = blockIdx.y * 128;

    int lane = tid & 31;
    int g = lane >> 2, t = lane & 3;
    int wid = tid >> 5;
    int wm = (wid & 1) * 64;
    int wn = (wid >> 1) * 32;

    float acc[4][4][4];
#pragma unroll
    for (int i = 0; i < 4; i++)
#pragma unroll
        for (int j = 0; j < 4; j++)
#pragma unroll
            for (int q = 0; q < 4; q++) acc[i][j][q] = 0.f;

    int ka0 = tid >> 5, ma0 = (tid & 31) * 4;
    int ka1 = (tid + 256) >> 5;
    int gm = m0 + ma0;
    bool gmv = gm < HW;

    uint32_t asb = (uint32_t)__cvta_generic_to_shared(As);
    uint32_t bsb = (uint32_t)__cvta_generic_to_shared(Bs);
    uint32_t adst0 = asb + (uint32_t)(ka0 * SPAD + ma0) * 4;
    uint32_t adst1 = asb + (uint32_t)(ka1 * SPAD + ma0) * 4;
    uint32_t bdst0 = bsb + (uint32_t)(ka0 * SPAD + ma0) * 4;
    uint32_t bdst1 = bsb + (uint32_t)(ka1 * SPAD + ma0) * 4;
    const uint32_t sbytes = STAGEF * 4;

    const int NKT = 16;
#pragma unroll
    for (int s = 0; s < 2; s++) {
        int c0 = s * 16;
        cpa16(adst0 + s * sbytes, Ag + (size_t)(c0 + ka0) * HW + gm, gmv);
        cpa16(adst1 + s * sbytes, Ag + (size_t)(c0 + ka1) * HW + gm, gmv);
        cpa16(bdst0 + s * sbytes, Bg + (size_t)(c0 + ka0) * HC_ + n0 + ma0, true);
        cpa16(bdst1 + s * sbytes, Bg + (size_t)(c0 + ka1) * HC_ + n0 + ma0, true);
        CP_COMMIT();
    }

    int buf = 0;
    for (int kt = 0; kt < NKT; kt++) {
        CP_WAIT1();
        __syncthreads();
        if (kt + 2 < NKT) {
            int s = buf + 2; if (s >= 3) s -= 3;
            int c0 = (kt + 2) * 16;
            cpa16(adst0 + s * sbytes, Ag + (size_t)(c0 + ka0) * HW + gm, gmv);
            cpa16(adst1 + s * sbytes, Ag + (size_t)(c0 + ka1) * HW + gm, gmv);
            cpa16(bdst0 + s * sbytes, Bg + (size_t)(c0 + ka0) * HC_ + n0 + ma0, true);
            cpa16(bdst1 + s * sbytes, Bg + (size_t)(c0 + ka1) * HC_ + n0 + ma0, true);
        }
        CP_COMMIT();

        const float* Ab = As + buf * STAGEF;
        const float* Bb = Bs + buf * STAGEF;
#pragma unroll
        for (int ks = 0; ks < 2; ks++) {
            int kk = ks * 8;
            uint32_t af[4][4], bf[4][2];
#pragma unroll
            for (int mf = 0; mf < 4; mf++) {
                int m = wm + mf * 16 + g;
                af[mf][0] = __float_as_uint(Ab[(kk + t) * SPAD + m]);
                af[mf][1] = __float_as_uint(Ab[(kk + t) * SPAD + m + 8]);
                af[mf][2] = __float_as_uint(Ab[(kk + t + 4) * SPAD + m]);
                af[mf][3] = __float_as_uint(Ab[(kk + t + 4) * SPAD + m + 8]);
            }
#pragma unroll
            for (int nf = 0; nf < 4; nf++) {
                int n = wn + nf * 8 + g;
                bf[nf][0] = __float_as_uint(Bb[(kk + t) * SPAD + n]);
                bf[nf][1] = __float_as_uint(Bb[(kk + t + 4) * SPAD + n]);
            }
#pragma unroll
            for (int mf = 0; mf < 4; mf++)
#pragma unroll
                for (int nf = 0; nf < 4; nf++) {
                    asm volatile(
                        "mma.sync.aligned.m16n8k8.row.col.f32.tf32.tf32.f32 "
                        "{%0,%1,%2,%3}, {%4,%5,%6,%7}, {%8,%9}, {%0,%1,%2,%3};"
                        : "+f"(acc[mf][nf][0]), "+f"(acc[mf][nf][1]),
                          "+f"(acc[mf][nf][2]), "+f"(acc[mf][nf][3])
                        : "r"(af[mf][0]), "r"(af[mf][1]), "r"(af[mf][2]), "r"(af[mf][3]),
                          "r"(bf[nf][0]), "r"(bf[nf][1]));
                }
        }
        buf = (buf == 2) ? 0 : buf + 1;
    }

    int z = n0 >> 8;
    int ob0 = n0 & 255;
#pragma unroll
    for (int mf = 0; mf < 4; mf++) {
        int m = m0 + wm + mf * 16 + g;
#pragma unroll
        for (int nf = 0; nf < 4; nf++) {
            int o = ob0 + wn + nf * 8 + 2 * t;
            if (m < HW) {
                float* dst = P + ((size_t)z * HW + m) * 256 + o;
                *(float2*)dst = make_float2(acc[mf][nf][0], acc[mf][nf][1]);
            }
            if (m + 8 < HW) {
                float* dst = P + ((size_t)z * HW + m + 8) * 256 + o;
                *(float2*)dst = make_float2(acc[mf][nf][2], acc[mf][nf][3]);
            }
        }
    }
}

// ---------------- ranged float4 cumsum of P along w ----------------
__global__ void k_prow(int lo, int hi) {
    int t = lo + blockIdx.x * 256 + threadIdx.x;
    if (t >= hi) return;
    int l = 0;
    while (t >= c_RCUM4[l + 1]) l++;
    int tt = t - c_RCUM4[l];
    int H = c_HH[l], W = c_WW[l];
    int o4 = (tt & 63) * 4;
    int r = tt >> 6;
    int h = r % H, z = r / H;
    float* p = g_P + c_POFF[l] + ((size_t)(z * H + h) * W) * 256 + o4;
    float4 a = make_float4(0, 0, 0, 0);
    for (int w = 0; w < W; w += 4) {
        float4 v0 = *(float4*)(p + (w + 0) * 256);
        float4 v1 = *(float4*)(p + (w + 1) * 256);
        float4 v2 = *(float4*)(p + (w + 2) * 256);
        float4 v3 = *(float4*)(p + (w + 3) * 256);
        a.x += v0.x; a.y += v0.y; a.z += v0.z; a.w += v0.w;
        *(float4*)(p + (w + 0) * 256) = a;
        a.x += v1.x; a.y += v1.y; a.z += v1.z; a.w += v1.w;
        *(float4*)(p + (w + 1) * 256) = a;
        a.x += v2.x; a.y += v2.y; a.z += v2.z; a.w += v2.w;
        *(float4*)(p + (w + 2) * 256) = a;
        a.x += v3.x; a.y += v3.y; a.z += v3.z; a.w += v3.w;
        *(float4*)(p + (w + 3) * 256) = a;
    }
}

// ---------------- ranged float4 cumsum of P along h, unroll 6 ----------------
__global__ void k_pcol(int lo, int hi) {
    int t = lo + blockIdx.x * 256 + threadIdx.x;
    if (t >= hi) return;
    int l = 0;
    while (t >= c_CCUM4[l + 1]) l++;
    int tt = t - c_CCUM4[l];
    int H = c_HH[l], W = c_WW[l];
    int o4 = (tt & 63) * 4;
    int r = tt >> 6;
    int w = r % W, z = r / W;
    float* p = g_P + c_POFF[l] + ((size_t)z * H * W + w) * 256 + o4;
    int stride = W * 256;
    float4 a = make_float4(0, 0, 0, 0);
    for (int h = 0; h < H; h += 6) {
        float4 v0 = *(float4*)(p + (h + 0) * stride);
        float4 v1 = *(float4*)(p + (h + 1) * stride);
        float4 v2 = *(float4*)(p + (h + 2) * stride);
        float4 v3 = *(float4*)(p + (h + 3) * stride);
        float4 v4 = *(float4*)(p + (h + 4) * stride);
        float4 v5 = *(float4*)(p + (h + 5) * stride);
        a.x += v0.x; a.y += v0.y; a.z += v0.z; a.w += v0.w;
        *(float4*)(p + (h + 0) * stride) = a;
        a.x += v1.x; a.y += v1.y; a.z += v1.z; a.w += v1.w;
        *(float4*)(p + (h + 1) * stride) = a;
        a.x += v2.x; a.y += v2.y; a.z += v2.z; a.w += v2.w;
        *(float4*)(p + (h + 2) * stride) = a;
        a.x += v3.x; a.y += v3.y; a.z += v3.z; a.w += v3.w;
        *(float4*)(p + (h + 3) * stride) = a;
        a.x += v4.x; a.y += v4.y; a.z += v4.z; a.w += v4.w;
        *(float4*)(p + (h + 4) * stride) = a;
        a.x += v5.x; a.y += v5.y; a.z += v5.z; a.w += v5.w;
        *(float4*)(p + (h + 5) * stride) = a;
    }
}

// ---------------- fused gather (dedup-table-driven), level-ranged ----------------
__global__ __launch_bounds__(256) void k_gather(const float* __restrict__ bias, int lbase) {
    int n = blockIdx.x;
    int l = lbase + blockIdx.y;
    int o = threadIdx.x;
    int Hf = c_HH[l], Wf = c_WW[l];
    int HW = Hf * Wf;
    float areaF = (float)HW * 0.25f;
    const float* __restrict__ P = g_P + c_POFF[l];
    int d = n / NWC;

    const float* ct = g_ctab + (size_t)(l * NCELL + n) * 12;
    float4 cw = *(const float4*)ct;
    int4 co = *(const int4*)(ct + 4);
    float xw = ct[8];
    int ncol = ((const int*)ct)[9];

    float acc = bias[l * 256 + o];

    const float* tab = g_rtab + (size_t)((l * NZ) * ND + d) * 12;
#pragma unroll
    for (int z = 0; z < NZ; z++, tab += ND * 12) {
        float4 rw = *(const float4*)tab;
        int4 ro = *(const int4*)(tab + 4);
        float yh = tab[8];
        int nrow = ((const int*)tab)[9];
        float area = xw * yh * areaF + 1e-6f;
        if (!(area > 1e-6f)) continue;
        float inv = 1.0f / area;
        const float* Pz = P + (size_t)z * HW * 256 + o;

        const float* Pr0 = Pz + ro.x;
        float rs0 = cw.x * Pr0[co.x] + cw.y * Pr0[co.y];
        if (ncol > 2) rs0 += cw.z * Pr0[co.z];
        if (ncol > 3) rs0 += cw.w * Pr0[co.w];
        const float* Pr1 = Pz + ro.y;
        float rs1 = cw.x * Pr1[co.x] + cw.y * Pr1[co.y];
        if (ncol > 2) rs1 += cw.z * Pr1[co.z];
        if (ncol > 3) rs1 += cw.w * Pr1[co.w];
        float s = rw.x * rs0 + rw.y * rs1;
        if (nrow > 2) {
            const float* Pr2 = Pz + ro.z;
            float rs2 = cw.x * Pr2[co.x] + cw.y * Pr2[co.y];
            if (ncol > 2) rs2 += cw.z * Pr2[co.z];
            if (ncol > 3) rs2 += cw.w * Pr2[co.w];
            s += rw.z * rs2;
        }
        if (nrow > 3) {
            const float* Pr3 = Pz + ro.w;
            float rs3 = cw.x * Pr3[co.x] + cw.y * Pr3[co.y];
            if (ncol > 2) rs3 += cw.z * Pr3[co.z];
            if (ncol > 3) rs3 += cw.w * Pr3[co.w];
            s += rw.w * rs3;
        }
        acc += inv * s;
    }
    int w = n - d * NWC;
    int sp = w * ND + d;
    g_xcat[(l * 256 + o) * NCELL + sp] = fmaxf(acc, 0.0f);
}

// ---------------- channel means (float4) ----------------
__global__ void k_colmean() {
    int g = blockIdx.x;
    const float4* p = (const float4*)(g_xcat + (size_t)g * NCELL);
    float s = 0.f;
    for (int i = threadIdx.x; i < NCELL / 4; i += 256) {
        float4 v = p[i];
        s += v.x + v.y + v.z + v.w;
    }
    __shared__ float sm[256];
    sm[threadIdx.x] = s;
    __syncthreads();
    for (int st = 128; st > 0; st >>= 1) {
        if (threadIdx.x < st) sm[threadIdx.x] += sm[threadIdx.x + st];
        __syncthreads();
    }
    if (threadIdx.x == 0) g_colmean[g] = sm[0] * (1.0f / (float)NCELL);
}

__global__ void k_att(const float* __restrict__ aw, const float* __restrict__ ab) {
    __shared__ float cm[IMC_];
    int l = blockIdx.x, o = threadIdx.x;
    cm[o] = g_colmean[l * IMC_ + o];
    __syncthreads();
    float acc = ab[o];
    for (int c = 0; c < IMC_; c++) acc += cm[c] * aw[o * IMC_ + c];
    g_sig[l * IMC_ + o] = 1.0f / (1.0f + expf(-acc));
}

// ---------------- fold attention + transpose conv1 weights -> tf32 [k][o] ----------------
__global__ void k_wscale(const float* __restrict__ w) {
    int idx = blockIdx.x * 256 + threadIdx.x;
    if (idx >= CATC * 9 * IMC_) return;
    int o = idx & 255;
    int t = idx >> 8;
    int kk = t % 9;
    int cin = t / 9;
    g_w1s[idx] = to_tf32(w[(o * CATC + cin) * 9 + kk] * g_sig[cin]);
}

// ---------------- implicit-GEMM tf32 conv (3x3, pad 1), split-K partials ----------------
#define APAD 68
#define BPAD 132
template<int STRIDE, int IH, int IW, int CONV1, int KCHUNK>
__global__ __launch_bounds__(256) void k_convmma() {
    const float* __restrict__ src = CONV1 ? g_xcat : g_y1;
    const float* __restrict__ wt  = CONV1 ? g_w1s : g_w2p;
    float* __restrict__ part = (CONV1 ? g_c1part : g_c2part) + (size_t)blockIdx.z * IMC_ * OSP;

    __shared__ float As[2][16 * APAD];
    __shared__ float Bs[2][16 * BPAD];

    int tid = threadIdx.x;
    int m0 = blockIdx.x * 64;
    int n0 = blockIdx.y * 128;
    int kbase = blockIdx.z * KCHUNK;

    int lane = tid & 31;
    int g = lane >> 2, t4 = lane & 3;
    int wid = tid >> 5;
    int wm = (wid & 1) * 32;
    int wn = (wid >> 1) * 32;

    int ma = tid & 63;
    int kqa = tid >> 6;
    int m = m0 + ma;
    bool mv = m < OSP;
    int mq = mv ? m : 0;
    int oh = mq / OW1, ow = mq - oh * OW1;
    int ihb = STRIDE * oh - 1, iwb = STRIDE * ow - 1;

    int nb = (tid & 31) * 4;
    int kqb = tid >> 5;

    float acc[2][4][4];
#pragma unroll
    for (int i = 0; i < 2; i++)
#pragma unroll
        for (int j = 0; j < 4; j++)
#pragma unroll
            for (int q = 0; q < 4; q++) acc[i][j][q] = 0.f;

    {
#pragma unroll
        for (int i = 0; i < 4; i++) {
            int kg = kbase + kqa * 4 + i;
            int cin = kg / 9; int r = kg - cin * 9;
            int ky = r / 3, kx = r - ky * 3;
            int ih = ihb + ky, iw = iwb + kx;
            bool ok = mv && ih >= 0 && ih < IH && iw >= 0 && iw < IW;
            float v = ok ? src[(size_t)cin * (IH * IW) + ih * IW + iw] : 0.f;
            As[0][(kqa * 4 + i) * APAD + ma] = to_tf32(v);
        }
#pragma unroll
        for (int p = 0; p < 2; p++) {
            int kk = kqb + p * 8;
            *(float4*)&Bs[0][kk * BPAD + nb] = *(const float4*)(wt + (size_t)(kbase + kk) * 256 + n0 + nb);
        }
    }
    __syncthreads();

    const int NT = KCHUNK / 16;
    for (int kt = 0; kt < NT; kt++) {
        int buf = kt & 1;
        float pa[4];
        float4 pb[2];
        if (kt + 1 < NT) {
            int k0n = kbase + (kt + 1) * 16;
#pragma unroll
            for (int i = 0; i < 4; i++) {
                int kg = k0n + kqa * 4 + i;
                int cin = kg / 9; int r = kg - cin * 9;
                int ky = r / 3, kx = r - ky * 3;
                int ih = ihb + ky, iw = iwb + kx;
                bool ok = mv && ih >= 0 && ih < IH && iw >= 0 && iw < IW;
                pa[i] = ok ? src[(size_t)cin * (IH * IW) + ih * IW + iw] : 0.f;
            }
#pragma unroll
            for (int p = 0; p < 2; p++) {
                int kk = kqb + p * 8;
                pb[p] = *(const float4*)(wt + (size_t)(k0n + kk) * 256 + n0 + nb);
            }
        }
#pragma unroll
        for (int ks = 0; ks < 2; ks++) {
            int kk = ks * 8;
            uint32_t af[2][4], bf[4][2];
#pragma unroll
            for (int mf = 0; mf < 2; mf++) {
                int mm = wm + mf * 16 + g;
                af[mf][0] = __float_as_uint(As[buf][(kk + t4) * APAD + mm]);
                af[mf][1] = __float_as_uint(As[buf][(kk + t4) * APAD + mm + 8]);
                af[mf][2] = __float_as_uint(As[buf][(kk + t4 + 4) * APAD + mm]);
                af[mf][3] = __float_as_uint(As[buf][(kk + t4 + 4) * APAD + mm + 8]);
            }
#pragma unroll
            for (int nf = 0; nf < 4; nf++) {
                int nn = wn + nf * 8 + g;
                bf[nf][0] = __float_as_uint(Bs[buf][(kk + t4) * BPAD + nn]);
                bf[nf][1] = __float_as_uint(Bs[buf][(kk + t4 + 4) * BPAD + nn]);
            }
#pragma unroll
            for (int mf = 0; mf < 2; mf++)
#pragma unroll
                for (int nf = 0; nf < 4; nf++) {
                    asm volatile(
                        "mma.sync.aligned.m16n8k8.row.col.f32.tf32.tf32.f32 "
                        "{%0,%1,%2,%3}, {%4,%5,%6,%7}, {%8,%9}, {%0,%1,%2,%3};"
                        : "+f"(acc[mf][nf][0]), "+f"(acc[mf][nf][1]),
                          "+f"(acc[mf][nf][2]), "+f"(acc[mf][nf][3])
                        : "r"(af[mf][0]), "r"(af[mf][1]), "r"(af[mf][2]), "r"(af[mf][3]),
                          "r"(bf[nf][0]), "r"(bf[nf][1]));
                }
        }
        if (kt + 1 < NT) {
            int b2 = buf ^ 1;
#pragma unroll
            for (int i = 0; i < 4; i++)
                As[b2][(kqa * 4 + i) * APAD + ma] = to_tf32(pa[i]);
#pragma unroll
            for (int p = 0; p < 2; p++)
                *(float4*)&Bs[b2][(kqb + p * 8) * BPAD + nb] = pb[p];
        }
        __syncthreads();
    }

#pragma unroll
    for (int mf = 0; mf < 2; mf++) {
        int mrow = m0 + wm + mf * 16 + g;
#pragma unroll
        for (int nf = 0; nf < 4; nf++) {
            int o = n0 + wn + nf * 8 + 2 * t4;
            if (mrow < OSP) {
                part[(size_t)o * OSP + mrow] = acc[mf][nf][0];
                part[(size_t)(o + 1) * OSP + mrow] = acc[mf][nf][1];
            }
            if (mrow + 8 < OSP) {
                part[(size_t)o * OSP + mrow + 8] = acc[mf][nf][2];
                part[(size_t)(o + 1) * OSP + mrow + 8] = acc[mf][nf][3];
            }
        }
    }
}

__global__ void k_c1red(const float* __restrict__ bg, const float* __restrict__ bb,
                        const float* __restrict__ bm, const float* __restrict__ bv) {
    int idx = blockIdx.x * 256 + threadIdx.x;
    if (idx >= IMC_ * OSP) return;
    int o = idx / OSP;
    float s = 0.f;
#pragma unroll
    for (int p = 0; p < 8; p++) s += g_c1part[(size_t)p * IMC_ * OSP + idx];
    float sc = bg[o] / sqrtf(bv[o] + 1e-5f);
    g_y1[idx] = fmaxf((s - bm[o]) * sc + bb[o], 0.f);
}

__global__ void k_c2red(const float* __restrict__ bg, const float* __restrict__ bb,
                        const float* __restrict__ bm, const float* __restrict__ bv,
                        float* __restrict__ out) {
    int idx = blockIdx.x * 256 + threadIdx.x;
    if (idx >= IMC_ * OSP) return;
    int o = idx / OSP;
    float s = 0.f;
#pragma unroll
    for (int p = 0; p < 4; p++) s += g_c2part[(size_t)p * IMC_ * OSP + idx];
    float sc = bg[o] / sqrtf(bv[o] + 1e-5f);
    out[idx] = fmaxf((s - bm[o]) * sc + bb[o], 0.f);
}

// ---------------- launch (two-stream overlap of L0 and L1-4 chains) ----------------
extern "C" void kernel_launch(void* const* d_in, const int* in_sizes, int n_in,
                              void* d_out, int out_size) {
    (void)in_sizes; (void)n_in; (void)out_size;
    const float* f0 = (const float*)d_in[0];
    const float* f1 = (const float*)d_in[1];
    const float* f2 = (const float*)d_in[2];
    const float* f3 = (const float*)d_in[3];
    const float* f4 = (const float*)d_in[4];
    const float* calib = (const float*)d_in[5];
    const float* oftw  = (const float*)d_in[6];
    const float* oftb  = (const float*)d_in[7];
    const float* attw  = (const float*)d_in[8];
    const float* attb  = (const float*)d_in[9];
    const float* c1w   = (const float*)d_in[10];
    const float* b1g   = (const float*)d_in[11];
    const float* b1b   = (const float*)d_in[12];
    const float* b1m   = (const float*)d_in[13];
    const float* b1v   = (const float*)d_in[14];
    const float* c2w   = (const float*)d_in[15];
    const float* b2g   = (const float*)d_in[16];
    const float* b2b   = (const float*)d_in[17];
    const float* b2m   = (const float*)d_in[18];
    const float* b2v   = (const float*)d_in[19];
    float* out = (float*)d_out;

    static cudaStream_t s2 = []() {
        cudaStream_t s; cudaStreamCreateWithFlags(&s, cudaStreamNonBlocking); return s;
    }();
    static cudaEvent_t ev_root = []() {
        cudaEvent_t e; cudaEventCreateWithFlags(&e, cudaEventDisableTiming); return e;
    }();
    static cudaEvent_t ev_pg = []() {
        cudaEvent_t e; cudaEventCreateWithFlags(&e, cudaEventDisableTiming); return e;
    }();
    static cudaEvent_t ev_b = []() {
        cudaEvent_t e; cudaEventCreateWithFlags(&e, cudaEventDisableTiming); return e;
    }();

    // fork s2 from the (captured) default stream
    cudaEventRecord(ev_root, 0);
    cudaStreamWaitEvent(s2, ev_root, 0);

    // s2: tap tables (independent of GEMM)
    k_tab<<<(5 * NCELL + 5 * NZ * ND + 255) / 256, 256, 0, s2>>>(calib);

    // main: weights + GEMM
    k_permw<<<(5 * 256 * HC_ + IMC_ * 9 * IMC_ + 255) / 256, 256>>>(oftw, c2w);
    const int pg_smem = STAGES * 2 * 16 * SPAD * 4;   // 52224 B
    cudaFuncSetAttribute(k_pgemm, cudaFuncAttributeMaxDynamicSharedMemorySize, pg_smem);
    k_pgemm<<<dim3(320, 18), 256, pg_smem>>>(f0, f1, f2, f3, f4);
    cudaEventRecord(ev_pg, 0);

    // s2: levels 1-4 chain (waits for pgemm)
    cudaStreamWaitEvent(s2, ev_pg, 0);
    k_prow<<<(107136 - 55296 + 255) / 256, 256, 0, s2>>>(55296, 107136);
    k_pcol<<<(357120 - 184320 + 255) / 256, 256, 0, s2>>>(184320, 357120);
    k_gather<<<dim3(NCELL, 4), 256, 0, s2>>>(oftb, 1);
    cudaEventRecord(ev_b, s2);

    // main: level 0 chain
    k_prow<<<(55296 + 255) / 256, 256>>>(0, 55296);
    k_pcol<<<(184320 + 255) / 256, 256>>>(0, 184320);
    k_gather<<<dim3(NCELL, 1), 256>>>(oftb, 0);

    // join
    cudaStreamWaitEvent(0, ev_b, 0);

    k_colmean<<<CATC, 256>>>();
    k_att<<<5, 256>>>(attw, attb);
    k_wscale<<<(CATC * 9 * IMC_ + 255) / 256, 256>>>(c1w);

    // conv1: K = 1280*9 = 11520, split-K 8 (chunk 1440)
    k_convmma<2, NWC, ND, 1, 1440><<<dim3((OSP + 63) / 64, 2, 8), 256>>>();
    k_c1red<<<(IMC_ * OSP + 255) / 256, 256>>>(b1g, b1b, b1m, b1v);
    // conv2: K = 256*9 = 2304, split-K 4 (chunk 576)
    k_convmma<1, OH1, OW1, 0, 576><<<dim3((OSP + 63) / 64, 2, 4), 256>>>();
    k_c2red<<<(IMC_ * OSP + 255) / 256, 256>>>(b2g, b2b, b2m, b2v, out);
}